// round 5
// baseline (speedup 1.0000x reference)
#include <cuda_runtime.h>

#define B_ 4
#define D_ 8
#define F_ 256
#define C_ 512
#define R_ 64
#define NPOS (B_*D_*F_)   /* 8192 */
#define NB (D_*F_)        /* 2048 keys per batch */

// Scratch (static device allocations are allowed; runtime allocs are not)
__device__ float g_Q[NPOS * R_];    // 2 MB
__device__ float g_K[NPOS * R_];    // 2 MB
__device__ float g_V[NPOS * C_];    // 16 MB
__device__ float g_Wt[NPOS * F_];   // 8 MB  (unnormalized attn weights, g-folded)
__device__ float g_Y1[NPOS * C_];   // 16 MB

// ---------------------------------------------------------------------------
// Generic GEMM: C[M,N] = A[M,K] @ W[K,N] + bias[N]
// 64x64 block tile, 256 threads, 4x4 per-thread microtile, K-chunks of 16.
// ---------------------------------------------------------------------------
__global__ __launch_bounds__(256) void gemm_bias_kernel(
    const float* __restrict__ A, const float* __restrict__ W,
    const float* __restrict__ bias, float* __restrict__ Cout,
    int M, int N, int K)
{
    __shared__ float As[16][68];   // [k][m], padded (68*4B = 17*16B keeps 16B align)
    __shared__ float Bs[16][64];   // [k][n]

    const int tid = threadIdx.x;
    const int tx = tid & 15, ty = tid >> 4;
    const int m0 = blockIdx.x * 64;
    const int n0 = blockIdx.y * 64;

    const int la_m = tid >> 2;
    const int la_k = (tid & 3) << 2;
    const int lb_k = tid >> 4;
    const int lb_n = (tid & 15) << 2;

    float acc[4][4] = {};

    for (int k0 = 0; k0 < K; k0 += 16) {
        float4 av = *(const float4*)&A[(m0 + la_m) * K + (k0 + la_k)];
        float4 bv = *(const float4*)&W[(k0 + lb_k) * N + (n0 + lb_n)];
        __syncthreads();
        As[la_k + 0][la_m] = av.x;
        As[la_k + 1][la_m] = av.y;
        As[la_k + 2][la_m] = av.z;
        As[la_k + 3][la_m] = av.w;
        *(float4*)&Bs[lb_k][lb_n] = bv;
        __syncthreads();
#pragma unroll
        for (int kk = 0; kk < 16; kk++) {
            float4 a4 = *(const float4*)&As[kk][ty << 2];
            float4 b4 = *(const float4*)&Bs[kk][tx << 2];
            float ar[4] = {a4.x, a4.y, a4.z, a4.w};
            float br[4] = {b4.x, b4.y, b4.z, b4.w};
#pragma unroll
            for (int i = 0; i < 4; i++)
#pragma unroll
                for (int j = 0; j < 4; j++)
                    acc[i][j] += ar[i] * br[j];
        }
    }

    float4 bb = *(const float4*)&bias[n0 + (tx << 2)];
    float bbr[4] = {bb.x, bb.y, bb.z, bb.w};
#pragma unroll
    for (int i = 0; i < 4; i++) {
        int row = m0 + (ty << 2) + i;
        float4 o;
        o.x = acc[i][0] + bbr[0];
        o.y = acc[i][1] + bbr[1];
        o.z = acc[i][2] + bbr[2];
        o.w = acc[i][3] + bbr[3];
        *(float4*)&Cout[row * N + n0 + (tx << 2)] = o;
    }
}

// ---------------------------------------------------------------------------
// Scores + softmax-numerator fold over key depth g.
// Block: 32 queries (fixed batch) x 128 key-f columns; loops g=0..7, keeping
// w[h] = sum_g exp(q . K[g,h]) in registers. Writes unnormalized weights.
// Softmax is shift-invariant and |e| <~ 9 here, so no max subtraction needed.
// Grid: (F_/128=2, NB/32=64, B_=4), 256 threads.
// ---------------------------------------------------------------------------
__global__ __launch_bounds__(256) void scores_kernel(
    const float* __restrict__ Q, const float* __restrict__ K,
    float* __restrict__ Wt)
{
    __shared__ float Qs[32][64];    // [q][r]
    __shared__ float Ks[128][65];   // [k][r], +1 pad to spread banks

    const int tid = threadIdx.x;
    const int b = blockIdx.z;
    const int q0 = blockIdx.y * 32;
    const int h0 = blockIdx.x * 128;
    const int tx = tid & 31, ty = tid >> 5;

#pragma unroll
    for (int it = 0; it < 2; it++) {
        int idx4 = tid + it * 256;
        int q = idx4 >> 4, r = (idx4 & 15) << 2;
        *(float4*)&Qs[q][r] = *(const float4*)&Q[(b * NB + q0 + q) * R_ + r];
    }

    float wacc[4][4] = {};

    for (int g = 0; g < 8; g++) {
        __syncthreads();   // first iter: publishes Qs; later: guards Ks reuse
#pragma unroll
        for (int it = 0; it < 8; it++) {
            int idx4 = tid + it * 256;
            int k = idx4 >> 4, r = (idx4 & 15) << 2;
            float4 v = *(const float4*)&K[(b * NB + g * F_ + h0 + k) * R_ + r];
            Ks[k][r + 0] = v.x;
            Ks[k][r + 1] = v.y;
            Ks[k][r + 2] = v.z;
            Ks[k][r + 3] = v.w;
        }
        __syncthreads();

        float acc[4][4] = {};
#pragma unroll 4
        for (int r = 0; r < 64; r++) {
            float a[4], bb[4];
#pragma unroll
            for (int j = 0; j < 4; j++) a[j] = Qs[(ty << 2) + j][r];
#pragma unroll
            for (int j = 0; j < 4; j++) bb[j] = Ks[(tx << 2) + j][r];
#pragma unroll
            for (int i = 0; i < 4; i++)
#pragma unroll
                for (int j = 0; j < 4; j++)
                    acc[i][j] += a[i] * bb[j];
        }
#pragma unroll
        for (int i = 0; i < 4; i++)
#pragma unroll
            for (int j = 0; j < 4; j++)
                wacc[i][j] += __expf(acc[i][j]);
    }

#pragma unroll
    for (int i = 0; i < 4; i++) {
        int row = b * NB + q0 + (ty << 2) + i;
        float4 o = {wacc[i][0], wacc[i][1], wacc[i][2], wacc[i][3]};
        *(float4*)&Wt[row * F_ + h0 + (tx << 2)] = o;
    }
}

// ---------------------------------------------------------------------------
// attn = (w/Z) @ V[b,d]; fused with residual + LayerNorm -> Y1.
// Block: 16 rows x full 512 cols (so LN is block-local). 256 threads,
// per-thread 2 rows x 16 cols (4 column groups of 4, interleaved by 128).
// Row scaling by 1/Z commuted to the epilogue.
// ---------------------------------------------------------------------------
__global__ __launch_bounds__(256) void attn_ln_kernel(
    const float* __restrict__ Wt, const float* __restrict__ V,
    const float* __restrict__ x, const float* __restrict__ g1,
    const float* __restrict__ b1, float* __restrict__ Y1)
{
    __shared__ float Bs[16][512];  // V k-tile; reused as t-value stash
    __shared__ float As[16][16];   // w tile [r][k]

    const int tid = threadIdx.x;
    const int row0 = blockIdx.x * 16;
    const int vbase = row0 & ~(F_ - 1);   // all 16 rows share (b,d)
    const int tx = tid & 31, ty = tid >> 5;
    const int ar = tid >> 4, ak = tid & 15;

    float acc[2][16] = {};

    for (int k0 = 0; k0 < F_; k0 += 16) {
        float a_v = Wt[(row0 + ar) * F_ + (k0 + ak)];
        float4 bv[8];
#pragma unroll
        for (int it = 0; it < 8; it++) {
            int idx4 = tid + it * 256;
            int k = idx4 >> 7, c = (idx4 & 127) << 2;
            bv[it] = *(const float4*)&V[(vbase + k0 + k) * C_ + c];
        }
        __syncthreads();
        As[ar][ak] = a_v;
#pragma unroll
        for (int it = 0; it < 8; it++) {
            int idx4 = tid + it * 256;
            int k = idx4 >> 7, c = (idx4 & 127) << 2;
            *(float4*)&Bs[k][c] = bv[it];
        }
        __syncthreads();
#pragma unroll
        for (int kk = 0; kk < 16; kk++) {
            float a0 = As[(ty << 1) + 0][kk];
            float a1 = As[(ty << 1) + 1][kk];
#pragma unroll
            for (int cg = 0; cg < 4; cg++) {
                float4 b4 = *(const float4*)&Bs[kk][cg * 128 + (tx << 2)];
                float br[4] = {b4.x, b4.y, b4.z, b4.w};
#pragma unroll
                for (int j = 0; j < 4; j++) {
                    acc[0][cg * 4 + j] += a0 * br[j];
                    acc[1][cg * 4 + j] += a1 * br[j];
                }
            }
        }
    }

    __syncthreads();
#pragma unroll
    for (int r = 0; r < 2; r++)
#pragma unroll
        for (int cg = 0; cg < 4; cg++) {
            float4 o = {acc[r][cg*4+0], acc[r][cg*4+1], acc[r][cg*4+2], acc[r][cg*4+3]};
            *(float4*)&Bs[(ty << 1) + r][cg * 128 + (tx << 2)] = o;
        }
    __syncthreads();

    const int lane = tid & 31, wp = tid >> 5;
#pragma unroll
    for (int rr = 0; rr < 2; rr++) {
        int r = (wp << 1) + rr;
        int grow = row0 + r;
        float z = 0.f;
#pragma unroll
        for (int j = 0; j < 8; j++) z += Wt[grow * F_ + j * 32 + lane];
#pragma unroll
        for (int off = 16; off; off >>= 1) z += __shfl_xor_sync(0xffffffffu, z, off);
        float invz = 1.0f / z;

        float vals[16], s1 = 0.f, s2 = 0.f;
#pragma unroll
        for (int j = 0; j < 16; j++) {
            int c = j * 32 + lane;
            float v = Bs[r][c] * invz + x[grow * C_ + c];
            vals[j] = v; s1 += v; s2 += v * v;
        }
#pragma unroll
        for (int off = 16; off; off >>= 1) {
            s1 += __shfl_xor_sync(0xffffffffu, s1, off);
            s2 += __shfl_xor_sync(0xffffffffu, s2, off);
        }
        float mean = s1 * (1.f / 512.f);
        float var = s2 * (1.f / 512.f) - mean * mean;
        float rstd = rsqrtf(var + 1e-3f);
#pragma unroll
        for (int j = 0; j < 16; j++) {
            int c = j * 32 + lane;
            Y1[grow * C_ + c] = (vals[j] - mean) * rstd * g1[c] + b1[c];
        }
    }
}

// ---------------------------------------------------------------------------
// y2 = LN(y1 + relu(y1 @ wm + bm)) -> final output. Same structure as above.
// ---------------------------------------------------------------------------
__global__ __launch_bounds__(256) void mlp_ln_kernel(
    const float* __restrict__ Y1, const float* __restrict__ Wm,
    const float* __restrict__ bm, const float* __restrict__ g2,
    const float* __restrict__ b2, float* __restrict__ Out)
{
    __shared__ float Bs[16][512];
    __shared__ float As[16][16];

    const int tid = threadIdx.x;
    const int row0 = blockIdx.x * 16;
    const int tx = tid & 31, ty = tid >> 5;
    const int ar = tid >> 4, ak = tid & 15;

    float acc[2][16] = {};

    for (int k0 = 0; k0 < C_; k0 += 16) {
        float a_v = Y1[(row0 + ar) * C_ + (k0 + ak)];
        float4 bv[8];
#pragma unroll
        for (int it = 0; it < 8; it++) {
            int idx4 = tid + it * 256;
            int k = idx4 >> 7, c = (idx4 & 127) << 2;
            bv[it] = *(const float4*)&Wm[(k0 + k) * C_ + c];
        }
        __syncthreads();
        As[ar][ak] = a_v;
#pragma unroll
        for (int it = 0; it < 8; it++) {
            int idx4 = tid + it * 256;
            int k = idx4 >> 7, c = (idx4 & 127) << 2;
            *(float4*)&Bs[k][c] = bv[it];
        }
        __syncthreads();
#pragma unroll
        for (int kk = 0; kk < 16; kk++) {
            float a0 = As[(ty << 1) + 0][kk];
            float a1 = As[(ty << 1) + 1][kk];
#pragma unroll
            for (int cg = 0; cg < 4; cg++) {
                float4 b4 = *(const float4*)&Bs[kk][cg * 128 + (tx << 2)];
                float br[4] = {b4.x, b4.y, b4.z, b4.w};
#pragma unroll
                for (int j = 0; j < 4; j++) {
                    acc[0][cg * 4 + j] += a0 * br[j];
                    acc[1][cg * 4 + j] += a1 * br[j];
                }
            }
        }
    }

    __syncthreads();
#pragma unroll
    for (int r = 0; r < 2; r++)
#pragma unroll
        for (int cg = 0; cg < 4; cg++) {
            float4 o = {acc[r][cg*4+0], acc[r][cg*4+1], acc[r][cg*4+2], acc[r][cg*4+3]};
            *(float4*)&Bs[(ty << 1) + r][cg * 128 + (tx << 2)] = o;
        }
    __syncthreads();

    const int lane = tid & 31, wp = tid >> 5;
#pragma unroll
    for (int rr = 0; rr < 2; rr++) {
        int r = (wp << 1) + rr;
        int grow = row0 + r;

        float vals[16], s1 = 0.f, s2 = 0.f;
#pragma unroll
        for (int j = 0; j < 16; j++) {
            int c = j * 32 + lane;
            float mlp = fmaxf(Bs[r][c] + bm[c], 0.f);
            float v = Y1[grow * C_ + c] + mlp;
            vals[j] = v; s1 += v; s2 += v * v;
        }
#pragma unroll
        for (int off = 16; off; off >>= 1) {
            s1 += __shfl_xor_sync(0xffffffffu, s1, off);
            s2 += __shfl_xor_sync(0xffffffffu, s2, off);
        }
        float mean = s1 * (1.f / 512.f);
        float var = s2 * (1.f / 512.f) - mean * mean;
        float rstd = rsqrtf(var + 1e-3f);
#pragma unroll
        for (int j = 0; j < 16; j++) {
            int c = j * 32 + lane;
            Out[grow * C_ + c] = (vals[j] - mean) * rstd * g2[c] + b2[c];
        }
    }
}

// ---------------------------------------------------------------------------
extern "C" void kernel_launch(void* const* d_in, const int* in_sizes, int n_in,
                              void* d_out, int out_size)
{
    const float* x  = (const float*)d_in[0];
    const float* wq = (const float*)d_in[1];
    const float* bq = (const float*)d_in[2];
    const float* wk = (const float*)d_in[3];
    const float* bk = (const float*)d_in[4];
    const float* wv = (const float*)d_in[5];
    const float* bv = (const float*)d_in[6];
    const float* wm = (const float*)d_in[7];
    const float* bm = (const float*)d_in[8];
    const float* g1 = (const float*)d_in[9];
    const float* b1 = (const float*)d_in[10];
    const float* g2 = (const float*)d_in[11];
    const float* b2 = (const float*)d_in[12];
    float* out = (float*)d_out;

    float *Qp, *Kp, *Vp, *Wp, *Y1p;
    cudaGetSymbolAddress((void**)&Qp,  g_Q);
    cudaGetSymbolAddress((void**)&Kp,  g_K);
    cudaGetSymbolAddress((void**)&Vp,  g_V);
    cudaGetSymbolAddress((void**)&Wp,  g_Wt);
    cudaGetSymbolAddress((void**)&Y1p, g_Y1);

    // 1) Projections
    gemm_bias_kernel<<<dim3(NPOS / 64, 1), 256>>>(x, wq, bq, Qp, NPOS, R_, C_);
    gemm_bias_kernel<<<dim3(NPOS / 64, 1), 256>>>(x, wk, bk, Kp, NPOS, R_, C_);
    gemm_bias_kernel<<<dim3(NPOS / 64, C_ / 64), 256>>>(x, wv, bv, Vp, NPOS, C_, C_);

    // 2) Scores + g-fold (unnormalized softmax numerators)
    scores_kernel<<<dim3(F_ / 128, NB / 32, B_), 256>>>(Qp, Kp, Wp);

    // 3) attn + residual + LN
    attn_ln_kernel<<<NPOS / 16, 256>>>(Wp, Vp, x, g1, b1, Y1p);

    // 4) MLP + residual + LN -> out
    mlp_ln_kernel<<<NPOS / 16, 256>>>(Y1p, wm, bm, g2, b2, out);
}

// round 8
// speedup vs baseline: 3.0241x; 3.0241x over previous
#include <cuda_runtime.h>
#include <cstdint>

#define B_ 4
#define D_ 8
#define F_ 256
#define C_ 512
#define NPOS 8192
#define NB 2048
#define BLKM 128
#define BLKN 128
#define BK 32

// ---------------- scratch (static device allocations only) ----------------
__device__ float g_Wqk[128 * 512];    // [n = q|k dim][k]  K-major
__device__ float g_bqk[128];
__device__ float g_WvT[512 * 512];    // wv^T  [c][k]
__device__ float g_WmT[512 * 512];    // wm^T  [c][k]
__device__ float g_QK[NPOS * 128];    // [pos][ q(64) | k(64) ]
__device__ float g_Vt[512 * NPOS];    // V transposed [c][pos]
__device__ float g_Wt[NPOS * 256];    // unnormalized folded attn weights
__device__ float g_attn[NPOS * 512];  // Wt @ V (unnormalized)
__device__ float g_Y1[NPOS * 512];
__device__ float g_mlp[NPOS * 512];

// ---------------- helpers ----------------
#define SWZ(x) ((x) ^ (((x) >> 3) & 0x70))

__device__ __forceinline__ uint32_t smem_u32(const void* p) {
    uint32_t a;
    asm("{ .reg .u64 t; cvta.to.shared.u64 t, %1; cvt.u32.u64 %0, t; }" : "=r"(a) : "l"(p));
    return a;
}
__device__ __forceinline__ uint32_t cvt_tf32(float f) {
    uint32_t r;
    asm("cvt.rna.tf32.f32 %0, %1;" : "=r"(r) : "f"(f));
    return r;
}
__device__ __forceinline__ void ldsm4(uint32_t& r0, uint32_t& r1, uint32_t& r2, uint32_t& r3,
                                      uint32_t a) {
    asm volatile("ldmatrix.sync.aligned.m8n8.x4.shared.b16 {%0,%1,%2,%3}, [%4];"
                 : "=r"(r0), "=r"(r1), "=r"(r2), "=r"(r3) : "r"(a));
}
// ldmatrix returns: r0=(rows0-7,k0-3) r1=(rows0-7,k4-7) r2=(rows8-15,k0-3) r3=(rows8-15,k4-7)
// tf32 m16n8k8 A fragment wants a0=(r0-7,k0-3) a1=(r8-15,k0-3) a2=(r0-7,k4-7) a3=(r8-15,k4-7)
// => pass a[0], a[2], a[1], a[3].  B fragment (per n8 tile) wants {k0-3, k4-7} = natural order.
__device__ __forceinline__ void mma8(float* c, const uint32_t* a, const uint32_t* b) {
    asm volatile(
        "mma.sync.aligned.m16n8k8.row.col.f32.tf32.tf32.f32 "
        "{%0,%1,%2,%3}, {%4,%5,%6,%7}, {%8,%9}, {%0,%1,%2,%3};"
        : "+f"(c[0]), "+f"(c[1]), "+f"(c[2]), "+f"(c[3])
        : "r"(a[0]), "r"(a[2]), "r"(a[1]), "r"(a[3]), "r"(b[0]), "r"(b[1]));
}

// ---------------------------------------------------------------------------
// prep: transpose weights to K-major [N][K]; concat q|k weights + biases.
// ---------------------------------------------------------------------------
__global__ void prep_kernel(const float* __restrict__ wq, const float* __restrict__ bq,
                            const float* __restrict__ wk, const float* __restrict__ bk,
                            const float* __restrict__ wv, const float* __restrict__ wm)
{
    int idx = blockIdx.x * blockDim.x + threadIdx.x;
    for (int i = idx; i < 512 * 512; i += gridDim.x * blockDim.x) {
        int c = i >> 9, k = i & 511;
        g_WvT[i] = wv[k * 512 + c];
        g_WmT[i] = wm[k * 512 + c];
        if (c < 64) {
            g_Wqk[c * 512 + k]        = wq[k * 64 + c];
            g_Wqk[(64 + c) * 512 + k] = wk[k * 64 + c];
        }
    }
    if (idx < 64) { g_bqk[idx] = bq[idx]; g_bqk[64 + idx] = bk[idx]; }
}

// ---------------------------------------------------------------------------
// Generic tf32 mma.sync GEMM: C[z][m][n] = sum_k A[z][m][k]*B[z][n][k] (+biases)
// Both operands K-major. 128x128 block tile, 8 warps (2x4), warp tile 64x32,
// K chunks of 32, SW128-swizzled smem, ldmatrix.x4 fragments.
// ---------------------------------------------------------------------------
__global__ __launch_bounds__(256, 2) void tc_gemm_kernel(
    const float* __restrict__ A, int lda, int sAz,
    const float* __restrict__ Bm, int ldb, int sBz,
    float* __restrict__ Cm, int ldc, int sCz,
    int Ktot, const float* __restrict__ colBias, const float* __restrict__ rowBias)
{
    __shared__ uint32_t smA[BLKM * BK];   // 16 KB
    __shared__ uint32_t smB[BLKN * BK];   // 16 KB

    const int tid = threadIdx.x, wid = tid >> 5, lane = tid & 31;
    const int m0w = (wid >> 2) * 64, n0w = (wid & 3) * 32;
    const int z = blockIdx.z;
    const float* Ab = A + (size_t)z * sAz + (size_t)(blockIdx.x * BLKM) * lda;
    const float* Bb = Bm + (size_t)z * sBz + (size_t)(blockIdx.y * BLKN) * ldb;

    const uint32_t sA = smem_u32(smA), sB = smem_u32(smB);
    const int frow = (lane & 7) + ((lane >> 4) & 1) * 8;   // fragment row within 16
    const int fseg = ((lane >> 3) & 1) * 16;               // +16B for k+4 half

    float acc[4][4][4] = {};
    const int nch = Ktot / BK;
    for (int kc = 0; kc < nch; kc++) {
        const int k0 = kc * BK;
#pragma unroll
        for (int i = 0; i < 4; i++) {                      // stage A (1024 f4)
            int idx = tid + i * 256;
            int row = idx >> 3, seg = idx & 7;
            float4 v = *(const float4*)(Ab + (size_t)row * lda + k0 + seg * 4);
            uint4 t = {cvt_tf32(v.x), cvt_tf32(v.y), cvt_tf32(v.z), cvt_tf32(v.w)};
            *(uint4*)((char*)smA + SWZ(row * 128 + seg * 16)) = t;
        }
#pragma unroll
        for (int i = 0; i < 4; i++) {                      // stage B
            int idx = tid + i * 256;
            int row = idx >> 3, seg = idx & 7;
            float4 v = *(const float4*)(Bb + (size_t)row * ldb + k0 + seg * 4);
            uint4 t = {cvt_tf32(v.x), cvt_tf32(v.y), cvt_tf32(v.z), cvt_tf32(v.w)};
            *(uint4*)((char*)smB + SWZ(row * 128 + seg * 16)) = t;
        }
        __syncthreads();
#pragma unroll
        for (int ks = 0; ks < 4; ks++) {
            uint32_t af[4][4], bf[2][4];
#pragma unroll
            for (int mf = 0; mf < 4; mf++)
                ldsm4(af[mf][0], af[mf][1], af[mf][2], af[mf][3],
                      sA + SWZ((m0w + mf * 16 + frow) * 128 + ks * 32 + fseg));
#pragma unroll
            for (int bi = 0; bi < 2; bi++)
                ldsm4(bf[bi][0], bf[bi][1], bf[bi][2], bf[bi][3],
                      sB + SWZ((n0w + bi * 16 + frow) * 128 + ks * 32 + fseg));
#pragma unroll
            for (int mf = 0; mf < 4; mf++)
#pragma unroll
                for (int nf = 0; nf < 4; nf++)
                    mma8(acc[mf][nf], af[mf], &bf[nf >> 1][(nf & 1) * 2]);
        }
        __syncthreads();
    }

    // epilogue: c0/c1 at (row, col..col+1), c2/c3 at (row+8, ...)
    const int lr = lane >> 2, lc = (lane & 3) * 2;
#pragma unroll
    for (int mf = 0; mf < 4; mf++)
#pragma unroll
        for (int nf = 0; nf < 4; nf++) {
            int row = blockIdx.x * BLKM + m0w + mf * 16 + lr;
            int col = blockIdx.y * BLKN + n0w + nf * 8 + lc;
            float cb0 = 0.f, cb1 = 0.f;
            if (colBias) { cb0 = colBias[col]; cb1 = colBias[col + 1]; }
            float rb0 = rowBias ? rowBias[row] : 0.f;
            float rb1 = rowBias ? rowBias[row + 8] : 0.f;
            float* p0 = Cm + (size_t)z * sCz + (size_t)row * ldc + col;
            float2 o0 = {acc[mf][nf][0] + cb0 + rb0, acc[mf][nf][1] + cb1 + rb0};
            float2 o1 = {acc[mf][nf][2] + cb0 + rb1, acc[mf][nf][3] + cb1 + rb1};
            *(float2*)p0 = o0;
            *(float2*)(p0 + (size_t)8 * ldc) = o1;
        }
}

// ---------------------------------------------------------------------------
// Scores + g-fold: per (batch, 64-query tile) x 256 keys-per-depth.
// Block tile M=64 (all warps share A), N=256 (warp n0 = wid*32). For each
// g: mma-accumulate 64x256x64 in registers, then fold += expf(acc).
// Never materializes the [B,D,F,D,F] score tensor.
// ---------------------------------------------------------------------------
__global__ __launch_bounds__(256, 1) void scores_tc_kernel(
    const float* __restrict__ QK, float* __restrict__ Wt)
{
    __shared__ uint32_t smQ[64 * BK];    // 8 KB
    __shared__ uint32_t smK[256 * BK];   // 32 KB

    const int tid = threadIdx.x, wid = tid >> 5, lane = tid & 31;
    const int n0w = wid * 32;
    const int b = blockIdx.y;
    const int qbase = b * NB + blockIdx.x * 64;
    const uint32_t sQ = smem_u32(smQ), sK = smem_u32(smK);
    const int frow = (lane & 7) + ((lane >> 4) & 1) * 8;
    const int fseg = ((lane >> 3) & 1) * 16;

    float fold[4][4][4] = {};
    for (int g = 0; g < 8; g++) {
        float acc[4][4][4] = {};
        const int kbase = b * NB + g * F_;
#pragma unroll
        for (int kc = 0; kc < 2; kc++) {
            const int k0 = kc * 32;
#pragma unroll
            for (int i = 0; i < 2; i++) {                  // stage Q 64x32
                int idx = tid + i * 256;
                int row = idx >> 3, seg = idx & 7;
                float4 v = *(const float4*)(QK + (size_t)(qbase + row) * 128 + k0 + seg * 4);
                uint4 t = {cvt_tf32(v.x), cvt_tf32(v.y), cvt_tf32(v.z), cvt_tf32(v.w)};
                *(uint4*)((char*)smQ + SWZ(row * 128 + seg * 16)) = t;
            }
#pragma unroll
            for (int i = 0; i < 8; i++) {                  // stage keys 256x32
                int idx = tid + i * 256;
                int row = idx >> 3, seg = idx & 7;
                float4 v = *(const float4*)(QK + (size_t)(kbase + row) * 128 + 64 + k0 + seg * 4);
                uint4 t = {cvt_tf32(v.x), cvt_tf32(v.y), cvt_tf32(v.z), cvt_tf32(v.w)};
                *(uint4*)((char*)smK + SWZ(row * 128 + seg * 16)) = t;
            }
            __syncthreads();
#pragma unroll
            for (int ks = 0; ks < 4; ks++) {
                uint32_t af[4][4], bf[2][4];
#pragma unroll
                for (int mf = 0; mf < 4; mf++)
                    ldsm4(af[mf][0], af[mf][1], af[mf][2], af[mf][3],
                          sQ + SWZ((mf * 16 + frow) * 128 + ks * 32 + fseg));
#pragma unroll
                for (int bi = 0; bi < 2; bi++)
                    ldsm4(bf[bi][0], bf[bi][1], bf[bi][2], bf[bi][3],
                          sK + SWZ((n0w + bi * 16 + frow) * 128 + ks * 32 + fseg));
#pragma unroll
                for (int mf = 0; mf < 4; mf++)
#pragma unroll
                    for (int nf = 0; nf < 4; nf++)
                        mma8(acc[mf][nf], af[mf], &bf[nf >> 1][(nf & 1) * 2]);
            }
            __syncthreads();
        }
#pragma unroll
        for (int mf = 0; mf < 4; mf++)
#pragma unroll
            for (int nf = 0; nf < 4; nf++)
#pragma unroll
                for (int r = 0; r < 4; r++)
                    fold[mf][nf][r] += __expf(acc[mf][nf][r]);
    }

    const int lr = lane >> 2, lc = (lane & 3) * 2;
#pragma unroll
    for (int mf = 0; mf < 4; mf++)
#pragma unroll
        for (int nf = 0; nf < 4; nf++) {
            int row = qbase + mf * 16 + lr;
            int col = n0w + nf * 8 + lc;
            float2 o0 = {fold[mf][nf][0], fold[mf][nf][1]};
            float2 o1 = {fold[mf][nf][2], fold[mf][nf][3]};
            *(float2*)(Wt + (size_t)row * 256 + col) = o0;
            *(float2*)(Wt + (size_t)(row + 8) * 256 + col) = o1;
        }
}

// ---------------------------------------------------------------------------
// Epilogue 1: y1 = LN(attnU/Z + x). One warp per row.
// ---------------------------------------------------------------------------
__global__ __launch_bounds__(256) void attn_ep_kernel(
    const float* __restrict__ Wt, const float* __restrict__ attn,
    const float* __restrict__ x, const float* __restrict__ g1,
    const float* __restrict__ b1, float* __restrict__ Y1)
{
    const int lane = threadIdx.x & 31;
    const size_t row = (size_t)blockIdx.x * 8 + (threadIdx.x >> 5);
    float z = 0.f;
#pragma unroll
    for (int j = 0; j < 8; j++) z += Wt[row * 256 + j * 32 + lane];
#pragma unroll
    for (int o = 16; o; o >>= 1) z += __shfl_xor_sync(0xffffffffu, z, o);
    float invz = 1.f / z;

    float vals[16], s1 = 0.f, s2 = 0.f;
#pragma unroll
    for (int j = 0; j < 16; j++) {
        int c = j * 32 + lane;
        float v = attn[row * 512 + c] * invz + x[row * 512 + c];
        vals[j] = v; s1 += v; s2 += v * v;
    }
#pragma unroll
    for (int o = 16; o; o >>= 1) {
        s1 += __shfl_xor_sync(0xffffffffu, s1, o);
        s2 += __shfl_xor_sync(0xffffffffu, s2, o);
    }
    float mean = s1 * (1.f / 512.f);
    float var = s2 * (1.f / 512.f) - mean * mean;
    float rstd = rsqrtf(var + 1e-3f);
#pragma unroll
    for (int j = 0; j < 16; j++) {
        int c = j * 32 + lane;
        Y1[row * 512 + c] = (vals[j] - mean) * rstd * g1[c] + b1[c];
    }
}

// ---------------------------------------------------------------------------
// Epilogue 2: out = LN(y1 + relu(mlp))   (bm already added in GEMM epilogue)
// ---------------------------------------------------------------------------
__global__ __launch_bounds__(256) void mlp_ep_kernel(
    const float* __restrict__ Y1, const float* __restrict__ mlp,
    const float* __restrict__ g2, const float* __restrict__ b2,
    float* __restrict__ Out)
{
    const int lane = threadIdx.x & 31;
    const size_t row = (size_t)blockIdx.x * 8 + (threadIdx.x >> 5);

    float vals[16], s1 = 0.f, s2 = 0.f;
#pragma unroll
    for (int j = 0; j < 16; j++) {
        int c = j * 32 + lane;
        float v = Y1[row * 512 + c] + fmaxf(mlp[row * 512 + c], 0.f);
        vals[j] = v; s1 += v; s2 += v * v;
    }
#pragma unroll
    for (int o = 16; o; o >>= 1) {
        s1 += __shfl_xor_sync(0xffffffffu, s1, o);
        s2 += __shfl_xor_sync(0xffffffffu, s2, o);
    }
    float mean = s1 * (1.f / 512.f);
    float var = s2 * (1.f / 512.f) - mean * mean;
    float rstd = rsqrtf(var + 1e-3f);
#pragma unroll
    for (int j = 0; j < 16; j++) {
        int c = j * 32 + lane;
        Out[row * 512 + c] = (vals[j] - mean) * rstd * g2[c] + b2[c];
    }
}

// ---------------------------------------------------------------------------
extern "C" void kernel_launch(void* const* d_in, const int* in_sizes, int n_in,
                              void* d_out, int out_size)
{
    const float* x  = (const float*)d_in[0];
    const float* wq = (const float*)d_in[1];
    const float* bq = (const float*)d_in[2];
    const float* wk = (const float*)d_in[3];
    const float* bk = (const float*)d_in[4];
    const float* wv = (const float*)d_in[5];
    const float* bv = (const float*)d_in[6];
    const float* wm = (const float*)d_in[7];
    const float* bm = (const float*)d_in[8];
    const float* g1 = (const float*)d_in[9];
    const float* b1 = (const float*)d_in[10];
    const float* g2 = (const float*)d_in[11];
    const float* b2 = (const float*)d_in[12];
    float* out = (float*)d_out;

    float *Wqkp, *bqkp, *WvTp, *WmTp, *QKp, *Vtp, *Wtp, *attnp, *Y1p, *mlpp;
    cudaGetSymbolAddress((void**)&Wqkp, g_Wqk);
    cudaGetSymbolAddress((void**)&bqkp, g_bqk);
    cudaGetSymbolAddress((void**)&WvTp, g_WvT);
    cudaGetSymbolAddress((void**)&WmTp, g_WmT);
    cudaGetSymbolAddress((void**)&QKp,  g_QK);
    cudaGetSymbolAddress((void**)&Vtp,  g_Vt);
    cudaGetSymbolAddress((void**)&Wtp,  g_Wt);
    cudaGetSymbolAddress((void**)&attnp, g_attn);
    cudaGetSymbolAddress((void**)&Y1p,  g_Y1);
    cudaGetSymbolAddress((void**)&mlpp, g_mlp);

    // 0) weight prep (transposes + q|k concat)
    prep_kernel<<<256, 256>>>(wq, bq, wk, bk, wv, wm);

    // 1) QK projection: [8192,128] = x . Wqk^T   (+bqk per col)
    tc_gemm_kernel<<<dim3(64, 1, 1), 256>>>(
        x, 512, 0, Wqkp, 512, 0, QKp, 128, 0, 512, bqkp, nullptr);

    // 2) V transposed: Vt[c][pos] = WvT[c][:] . x[pos][:]   (+bv per row=c)
    tc_gemm_kernel<<<dim3(4, 64, 1), 256>>>(
        WvTp, 512, 0, x, 512, 0, Vtp, NPOS, 0, 512, nullptr, bv);

    // 3) scores + g-fold -> unnormalized Wt [8192 x 256]
    scores_tc_kernel<<<dim3(32, 4, 1), 256>>>(QKp, Wtp);

    // 4) attnU[z] = Wt[z] @ Vt[:, z*256:+256]^T  per (b,d) slice z (32 slices)
    tc_gemm_kernel<<<dim3(2, 4, 32), 256>>>(
        Wtp, 256, 65536, Vtp, NPOS, 256, attnp, 512, 131072, 256, nullptr, nullptr);

    // 5) y1 = LN(attnU/Z + x)
    attn_ep_kernel<<<NPOS / 8, 256>>>(Wtp, attnp, x, g1, b1, Y1p);

    // 6) mlp = y1 @ wm + bm
    tc_gemm_kernel<<<dim3(64, 4, 1), 256>>>(
        Y1p, 512, 0, WmTp, 512, 0, mlpp, 512, 0, 512, bm, nullptr);

    // 7) out = LN(y1 + relu(mlp))
    mlp_ep_kernel<<<NPOS / 8, 256>>>(Y1p, mlpp, g2, b2, out);
}

// round 9
// speedup vs baseline: 4.2668x; 1.4109x over previous
#include <cuda_runtime.h>
#include <cstdint>

#define B_ 4
#define D_ 8
#define F_ 256
#define C_ 512
#define NPOS 8192
#define NB 2048
#define BLKM 128
#define BLKN 128
#define BK 32

// ---------------- scratch (static device allocations only) ----------------
__device__ float g_Wqk[128 * 512];    // [n = q|k dim][k]  K-major
__device__ float g_bqk[128];
__device__ float g_WvT[512 * 512];    // wv^T  [c][k]
__device__ float g_WmT[512 * 512];    // wm^T  [c][k]
__device__ float g_QK[NPOS * 128];    // [pos][ q(64) | k(64) ]
__device__ float g_Vt[512 * NPOS];    // V transposed [c][pos]
__device__ float g_Wt[NPOS * 256];    // unnormalized folded attn weights
__device__ float g_attn[NPOS * 512];  // Wt @ V (unnormalized)
__device__ float g_Y1[NPOS * 512];
__device__ float g_mlp[NPOS * 512];

// ---------------- helpers ----------------
#define SWZ(x) ((x) ^ (((x) >> 3) & 0x70))
#define CP16(dst, src) asm volatile("cp.async.cg.shared.global [%0], [%1], 16;" :: "r"(dst), "l"(src))
#define CPCOMMIT() asm volatile("cp.async.commit_group;" ::: "memory")
#define CPWAIT1() asm volatile("cp.async.wait_group 1;" ::: "memory")

__device__ __forceinline__ uint32_t smem_u32(const void* p) {
    uint32_t a;
    asm("{ .reg .u64 t; cvta.to.shared.u64 t, %1; cvt.u32.u64 %0, t; }" : "=r"(a) : "l"(p));
    return a;
}
__device__ __forceinline__ uint32_t cvt_tf32(float f) {
    uint32_t r;
    asm("cvt.rna.tf32.f32 %0, %1;" : "=r"(r) : "f"(f));
    return r;
}
__device__ __forceinline__ void ldsm4(uint32_t& r0, uint32_t& r1, uint32_t& r2, uint32_t& r3,
                                      uint32_t a) {
    asm volatile("ldmatrix.sync.aligned.m8n8.x4.shared.b16 {%0,%1,%2,%3}, [%4];"
                 : "=r"(r0), "=r"(r1), "=r"(r2), "=r"(r3) : "r"(a));
}
// ldmatrix reg order vs tf32 m16n8k8 A fragment: pass a[0], a[2], a[1], a[3].
__device__ __forceinline__ void mma8(float* c, const uint32_t* a, const uint32_t* b) {
    asm volatile(
        "mma.sync.aligned.m16n8k8.row.col.f32.tf32.tf32.f32 "
        "{%0,%1,%2,%3}, {%4,%5,%6,%7}, {%8,%9}, {%0,%1,%2,%3};"
        : "+f"(c[0]), "+f"(c[1]), "+f"(c[2]), "+f"(c[3])
        : "r"(a[0]), "r"(a[2]), "r"(a[1]), "r"(a[3]), "r"(b[0]), "r"(b[1]));
}

// ---------------------------------------------------------------------------
// prep: transpose weights to K-major [N][K]; concat q|k weights + biases.
// ---------------------------------------------------------------------------
__global__ void prep_kernel(const float* __restrict__ wq, const float* __restrict__ bq,
                            const float* __restrict__ wk, const float* __restrict__ bk,
                            const float* __restrict__ wv, const float* __restrict__ wm)
{
    int idx = blockIdx.x * blockDim.x + threadIdx.x;
    for (int i = idx; i < 512 * 512; i += gridDim.x * blockDim.x) {
        int c = i >> 9, k = i & 511;
        g_WvT[i] = wv[k * 512 + c];
        g_WmT[i] = wm[k * 512 + c];
        if (c < 64) {
            g_Wqk[c * 512 + k]        = wq[k * 64 + c];
            g_Wqk[(64 + c) * 512 + k] = wk[k * 64 + c];
        }
    }
    if (idx < 64) { g_bqk[idx] = bq[idx]; g_bqk[64 + idx] = bk[idx]; }
}

// ---------------------------------------------------------------------------
// cp.async stager for one 128x32 A chunk + 128x32 B chunk (raw fp32; HMMA
// truncates fp32->tf32 in hardware).
// ---------------------------------------------------------------------------
__device__ __forceinline__ void stage_ab(uint32_t sbase, int s,
                                         const float* Ab, int lda,
                                         const float* Bb, int ldb,
                                         int k0, int tid)
{
    uint32_t aoff = sbase + (uint32_t)s * 16384u;
    uint32_t boff = sbase + 32768u + (uint32_t)s * 16384u;
#pragma unroll
    for (int i = 0; i < 4; i++) {
        int idx = tid + i * 256, row = idx >> 3, seg = idx & 7;
        CP16(aoff + SWZ(row * 128 + seg * 16), Ab + (size_t)row * lda + k0 + seg * 4);
        CP16(boff + SWZ(row * 128 + seg * 16), Bb + (size_t)row * ldb + k0 + seg * 4);
    }
}

// ---------------------------------------------------------------------------
// Generic tf32 mma.sync GEMM: C[z][m][n] = sum_k A[z][m][k]*B[z][n][k] (+biases)
// 128x128 block tile, 8 warps (2x4), warp tile 64x32, K chunks of 32.
// cp.async double-buffered staging; SW128-swizzled smem; ldmatrix.x4.
// Dynamic smem: A stage0 @0, stage1 @16K; B stage0 @32K, stage1 @48K (64 KB).
// ---------------------------------------------------------------------------
__global__ __launch_bounds__(256, 2) void tc_gemm_kernel(
    const float* __restrict__ A, int lda, int sAz,
    const float* __restrict__ Bm, int ldb, int sBz,
    float* __restrict__ Cm, int ldc, int sCz,
    int Ktot, const float* __restrict__ colBias, const float* __restrict__ rowBias)
{
    extern __shared__ char dsm[];
    const uint32_t sbase = smem_u32(dsm);

    const int tid = threadIdx.x, wid = tid >> 5, lane = tid & 31;
    const int m0w = (wid >> 2) * 64, n0w = (wid & 3) * 32;
    const int z = blockIdx.z;
    const float* Ab = A + (size_t)z * sAz + (size_t)(blockIdx.x * BLKM) * lda;
    const float* Bb = Bm + (size_t)z * sBz + (size_t)(blockIdx.y * BLKN) * ldb;

    const int frow = (lane & 7) + ((lane >> 4) & 1) * 8;
    const int fseg = ((lane >> 3) & 1) * 16;

    float acc[4][4][4] = {};
    const int nch = Ktot / BK;

    stage_ab(sbase, 0, Ab, lda, Bb, ldb, 0, tid);
    CPCOMMIT();

    for (int kc = 0; kc < nch; kc++) {
        if (kc + 1 < nch)
            stage_ab(sbase, (kc + 1) & 1, Ab, lda, Bb, ldb, (kc + 1) * BK, tid);
        CPCOMMIT();
        CPWAIT1();
        __syncthreads();

        const uint32_t sA = sbase + (uint32_t)(kc & 1) * 16384u;
        const uint32_t sB = sbase + 32768u + (uint32_t)(kc & 1) * 16384u;
#pragma unroll
        for (int ks = 0; ks < 4; ks++) {
            uint32_t af[4][4], bf[2][4];
#pragma unroll
            for (int mf = 0; mf < 4; mf++)
                ldsm4(af[mf][0], af[mf][1], af[mf][2], af[mf][3],
                      sA + SWZ((m0w + mf * 16 + frow) * 128 + ks * 32 + fseg));
#pragma unroll
            for (int bi = 0; bi < 2; bi++)
                ldsm4(bf[bi][0], bf[bi][1], bf[bi][2], bf[bi][3],
                      sB + SWZ((n0w + bi * 16 + frow) * 128 + ks * 32 + fseg));
#pragma unroll
            for (int mf = 0; mf < 4; mf++)
#pragma unroll
                for (int nf = 0; nf < 4; nf++)
                    mma8(acc[mf][nf], af[mf], &bf[nf >> 1][(nf & 1) * 2]);
        }
        __syncthreads();
    }

    // epilogue: c0/c1 at (row, col..col+1), c2/c3 at (row+8, ...)
    const int lr = lane >> 2, lc = (lane & 3) * 2;
#pragma unroll
    for (int mf = 0; mf < 4; mf++)
#pragma unroll
        for (int nf = 0; nf < 4; nf++) {
            int row = blockIdx.x * BLKM + m0w + mf * 16 + lr;
            int col = blockIdx.y * BLKN + n0w + nf * 8 + lc;
            float cb0 = 0.f, cb1 = 0.f;
            if (colBias) { cb0 = colBias[col]; cb1 = colBias[col + 1]; }
            float rb0 = rowBias ? rowBias[row] : 0.f;
            float rb1 = rowBias ? rowBias[row + 8] : 0.f;
            float* p0 = Cm + (size_t)z * sCz + (size_t)row * ldc + col;
            float2 o0 = {acc[mf][nf][0] + cb0 + rb0, acc[mf][nf][1] + cb1 + rb0};
            float2 o1 = {acc[mf][nf][2] + cb0 + rb1, acc[mf][nf][3] + cb1 + rb1};
            *(float2*)p0 = o0;
            *(float2*)(p0 + (size_t)8 * ldc) = o1;
        }
}

// ---------------------------------------------------------------------------
// Scores + g-fold: block = 32 queries x 256 keys, 8 warps (warp n0 = wid*32).
// Q (32x64, rna-rounded) resident in smem; key chunks (256x32) cp.async
// double-buffered across 16 (g,kc) chunks. acc accumulates both kc of a g;
// fold += expf(acc) after kc==1. Never materializes the score tensor.
// Dynamic smem: Q kc0 @0 (4K), Q kc1 @4K; keys stage0 @8K, stage1 @40K (72 KB).
// ---------------------------------------------------------------------------
__global__ __launch_bounds__(256, 2) void scores_tc_kernel(
    const float* __restrict__ QK, float* __restrict__ Wt)
{
    extern __shared__ char dsm[];
    const uint32_t sbase = smem_u32(dsm);

    const int tid = threadIdx.x, wid = tid >> 5, lane = tid & 31;
    const int n0w = wid * 32;
    const int b = blockIdx.y;
    const int qbase = b * NB + blockIdx.x * 32;

    const int frow = (lane & 7) + ((lane >> 4) & 1) * 8;
    const int fseg = ((lane >> 3) & 1) * 16;

    // stage Q (rna-rounded; register path, conversion is free)
#pragma unroll
    for (int i = 0; i < 2; i++) {
        int idx = tid + i * 256;
        int row = idx >> 4, seg = idx & 15;            // row 0..31, seg 0..15 (k=seg*4)
        float4 v = *(const float4*)(QK + (size_t)(qbase + row) * 128 + seg * 4);
        uint4 t = {cvt_tf32(v.x), cvt_tf32(v.y), cvt_tf32(v.z), cvt_tf32(v.w)};
        uint32_t off = (uint32_t)((seg >> 3) * 4096) + SWZ(row * 128 + (seg & 7) * 16);
        *(uint4*)(dsm + off) = t;
    }

    // key chunk stager: chunk t -> g=t>>1, kc=t&1; 256 rows x 32 k
    const float* kb0 = QK + (size_t)b * NB * 128 + 64;
#define STAGE_KEYS(t)                                                          \
    do {                                                                       \
        const float* kb = kb0 + (size_t)((t) >> 1) * 256 * 128 + ((t) & 1) * 32; \
        uint32_t koff = sbase + 8192u + (uint32_t)((t) & 1) * 32768u;          \
        _Pragma("unroll")                                                      \
        for (int i = 0; i < 8; i++) {                                          \
            int idx = tid + i * 256, row = idx >> 3, seg = idx & 7;            \
            CP16(koff + SWZ(row * 128 + seg * 16), kb + (size_t)row * 128 + seg * 4); \
        }                                                                      \
    } while (0)

    float fold[2][4][4] = {};
    float acc[2][4][4];

    STAGE_KEYS(0);
    CPCOMMIT();

    for (int t = 0; t < 16; t++) {
        if (t + 1 < 16) STAGE_KEYS(t + 1);
        CPCOMMIT();
        CPWAIT1();
        __syncthreads();

        const int kc = t & 1;
        if (kc == 0) {
#pragma unroll
            for (int mf = 0; mf < 2; mf++)
#pragma unroll
                for (int nf = 0; nf < 4; nf++)
#pragma unroll
                    for (int r = 0; r < 4; r++) acc[mf][nf][r] = 0.f;
        }
        const uint32_t sQ = sbase + (uint32_t)kc * 4096u;
        const uint32_t sK = sbase + 8192u + (uint32_t)(t & 1) * 32768u;
#pragma unroll
        for (int ks = 0; ks < 4; ks++) {
            uint32_t af[2][4], bf[2][4];
#pragma unroll
            for (int mf = 0; mf < 2; mf++)
                ldsm4(af[mf][0], af[mf][1], af[mf][2], af[mf][3],
                      sQ + SWZ((mf * 16 + frow) * 128 + ks * 32 + fseg));
#pragma unroll
            for (int bi = 0; bi < 2; bi++)
                ldsm4(bf[bi][0], bf[bi][1], bf[bi][2], bf[bi][3],
                      sK + SWZ((n0w + bi * 16 + frow) * 128 + ks * 32 + fseg));
#pragma unroll
            for (int mf = 0; mf < 2; mf++)
#pragma unroll
                for (int nf = 0; nf < 4; nf++)
                    mma8(acc[mf][nf], af[mf], &bf[nf >> 1][(nf & 1) * 2]);
        }
        if (kc == 1) {
#pragma unroll
            for (int mf = 0; mf < 2; mf++)
#pragma unroll
                for (int nf = 0; nf < 4; nf++)
#pragma unroll
                    for (int r = 0; r < 4; r++)
                        fold[mf][nf][r] += __expf(acc[mf][nf][r]);
        }
        __syncthreads();
    }
#undef STAGE_KEYS

    const int lr = lane >> 2, lc = (lane & 3) * 2;
#pragma unroll
    for (int mf = 0; mf < 2; mf++)
#pragma unroll
        for (int nf = 0; nf < 4; nf++) {
            int row = qbase + mf * 16 + lr;
            int col = n0w + nf * 8 + lc;
            float2 o0 = {fold[mf][nf][0], fold[mf][nf][1]};
            float2 o1 = {fold[mf][nf][2], fold[mf][nf][3]};
            *(float2*)(Wt + (size_t)row * 256 + col) = o0;
            *(float2*)(Wt + (size_t)(row + 8) * 256 + col) = o1;
        }
}

// ---------------------------------------------------------------------------
// Epilogue 1: y1 = LN(attnU/Z + x). One warp per row.
// ---------------------------------------------------------------------------
__global__ __launch_bounds__(256) void attn_ep_kernel(
    const float* __restrict__ Wt, const float* __restrict__ attn,
    const float* __restrict__ x, const float* __restrict__ g1,
    const float* __restrict__ b1, float* __restrict__ Y1)
{
    const int lane = threadIdx.x & 31;
    const size_t row = (size_t)blockIdx.x * 8 + (threadIdx.x >> 5);
    float z = 0.f;
#pragma unroll
    for (int j = 0; j < 8; j++) z += Wt[row * 256 + j * 32 + lane];
#pragma unroll
    for (int o = 16; o; o >>= 1) z += __shfl_xor_sync(0xffffffffu, z, o);
    float invz = 1.f / z;

    float vals[16], s1 = 0.f, s2 = 0.f;
#pragma unroll
    for (int j = 0; j < 16; j++) {
        int c = j * 32 + lane;
        float v = attn[row * 512 + c] * invz + x[row * 512 + c];
        vals[j] = v; s1 += v; s2 += v * v;
    }
#pragma unroll
    for (int o = 16; o; o >>= 1) {
        s1 += __shfl_xor_sync(0xffffffffu, s1, o);
        s2 += __shfl_xor_sync(0xffffffffu, s2, o);
    }
    float mean = s1 * (1.f / 512.f);
    float var = s2 * (1.f / 512.f) - mean * mean;
    float rstd = rsqrtf(var + 1e-3f);
#pragma unroll
    for (int j = 0; j < 16; j++) {
        int c = j * 32 + lane;
        Y1[row * 512 + c] = (vals[j] - mean) * rstd * g1[c] + b1[c];
    }
}

// ---------------------------------------------------------------------------
// Epilogue 2: out = LN(y1 + relu(mlp))   (bm already added in GEMM epilogue)
// ---------------------------------------------------------------------------
__global__ __launch_bounds__(256) void mlp_ep_kernel(
    const float* __restrict__ Y1, const float* __restrict__ mlp,
    const float* __restrict__ g2, const float* __restrict__ b2,
    float* __restrict__ Out)
{
    const int lane = threadIdx.x & 31;
    const size_t row = (size_t)blockIdx.x * 8 + (threadIdx.x >> 5);

    float vals[16], s1 = 0.f, s2 = 0.f;
#pragma unroll
    for (int j = 0; j < 16; j++) {
        int c = j * 32 + lane;
        float v = Y1[row * 512 + c] + fmaxf(mlp[row * 512 + c], 0.f);
        vals[j] = v; s1 += v; s2 += v * v;
    }
#pragma unroll
    for (int o = 16; o; o >>= 1) {
        s1 += __shfl_xor_sync(0xffffffffu, s1, o);
        s2 += __shfl_xor_sync(0xffffffffu, s2, o);
    }
    float mean = s1 * (1.f / 512.f);
    float var = s2 * (1.f / 512.f) - mean * mean;
    float rstd = rsqrtf(var + 1e-3f);
#pragma unroll
    for (int j = 0; j < 16; j++) {
        int c = j * 32 + lane;
        Out[row * 512 + c] = (vals[j] - mean) * rstd * g2[c] + b2[c];
    }
}

// ---------------------------------------------------------------------------
extern "C" void kernel_launch(void* const* d_in, const int* in_sizes, int n_in,
                              void* d_out, int out_size)
{
    const float* x  = (const float*)d_in[0];
    const float* wq = (const float*)d_in[1];
    const float* bq = (const float*)d_in[2];
    const float* wk = (const float*)d_in[3];
    const float* bk = (const float*)d_in[4];
    const float* wv = (const float*)d_in[5];
    const float* bv = (const float*)d_in[6];
    const float* wm = (const float*)d_in[7];
    const float* bm = (const float*)d_in[8];
    const float* g1 = (const float*)d_in[9];
    const float* b1 = (const float*)d_in[10];
    const float* g2 = (const float*)d_in[11];
    const float* b2 = (const float*)d_in[12];
    float* out = (float*)d_out;

    float *Wqkp, *bqkp, *WvTp, *WmTp, *QKp, *Vtp, *Wtp, *attnp, *Y1p, *mlpp;
    cudaGetSymbolAddress((void**)&Wqkp, g_Wqk);
    cudaGetSymbolAddress((void**)&bqkp, g_bqk);
    cudaGetSymbolAddress((void**)&WvTp, g_WvT);
    cudaGetSymbolAddress((void**)&WmTp, g_WmT);
    cudaGetSymbolAddress((void**)&QKp,  g_QK);
    cudaGetSymbolAddress((void**)&Vtp,  g_Vt);
    cudaGetSymbolAddress((void**)&Wtp,  g_Wt);
    cudaGetSymbolAddress((void**)&attnp, g_attn);
    cudaGetSymbolAddress((void**)&Y1p,  g_Y1);
    cudaGetSymbolAddress((void**)&mlpp, g_mlp);

    const int GEMM_SMEM = 65536;                 // 2 x (16K A + 16K B)
    const int SC_SMEM   = 8192 + 2 * 32768;      // Q + 2 key stages = 72 KB
    cudaFuncSetAttribute(tc_gemm_kernel, cudaFuncAttributeMaxDynamicSharedMemorySize, GEMM_SMEM);
    cudaFuncSetAttribute(scores_tc_kernel, cudaFuncAttributeMaxDynamicSharedMemorySize, SC_SMEM);

    // 0) weight prep (transposes + q|k concat)
    prep_kernel<<<256, 256>>>(wq, bq, wk, bk, wv, wm);

    // 1) QK projection: [8192,128] = x . Wqk^T   (+bqk per col)
    tc_gemm_kernel<<<dim3(64, 1, 1), 256, GEMM_SMEM>>>(
        x, 512, 0, Wqkp, 512, 0, QKp, 128, 0, 512, bqkp, nullptr);

    // 2) V transposed: Vt[c][pos] = WvT[c][:] . x[pos][:]   (+bv per row=c)
    tc_gemm_kernel<<<dim3(4, 64, 1), 256, GEMM_SMEM>>>(
        WvTp, 512, 0, x, 512, 0, Vtp, NPOS, 0, 512, nullptr, bv);

    // 3) scores + g-fold -> unnormalized Wt [8192 x 256]
    scores_tc_kernel<<<dim3(64, 4, 1), 256, SC_SMEM>>>(QKp, Wtp);

    // 4) attnU[z] = Wt[z] @ Vt[:, z*256:+256]^T  per (b,d) slice z (32 slices)
    tc_gemm_kernel<<<dim3(2, 4, 32), 256, GEMM_SMEM>>>(
        Wtp, 256, 65536, Vtp, NPOS, 256, attnp, 512, 131072, 256, nullptr, nullptr);

    // 5) y1 = LN(attnU/Z + x)
    attn_ep_kernel<<<NPOS / 8, 256>>>(Wtp, attnp, x, g1, b1, Y1p);

    // 6) mlp = y1 @ wm + bm
    tc_gemm_kernel<<<dim3(64, 4, 1), 256, GEMM_SMEM>>>(
        Y1p, 512, 0, WmTp, 512, 0, mlpp, 512, 0, 512, bm, nullptr);

    // 7) out = LN(y1 + relu(mlp))
    mlp_ep_kernel<<<NPOS / 8, 256>>>(Y1p, mlpp, g2, b2, out);
}

// round 13
// speedup vs baseline: 4.3341x; 1.0158x over previous
#include <cuda_runtime.h>
#include <cstdint>

#define B_ 4
#define D_ 8
#define F_ 256
#define C_ 512
#define NPOS 8192
#define NB 2048
#define BLKM 128
#define BLKN 128
#define BK 32

// ---------------- scratch (static device allocations only) ----------------
__device__ float g_Wqk[128 * 512];    // [n = q|k dim][k]  K-major
__device__ float g_bqk[128];
__device__ float g_WvT[512 * 512];    // wv^T  [c][k]
__device__ float g_WmT[512 * 512];    // wm^T  [c][k]
__device__ float g_QK[NPOS * 128];    // [pos][ q(64) | k(64) ]
__device__ float g_Vt[512 * NPOS];    // V transposed [c][pos]
__device__ float g_Wt[NPOS * 256];    // unnormalized folded attn weights
__device__ float g_attn[NPOS * 512];  // Wt @ V (unnormalized)
__device__ float g_Y1[NPOS * 512];
__device__ float g_mlp[NPOS * 512];

// ---------------- helpers ----------------
#define SWZ(x) ((x) ^ (((x) >> 3) & 0x70))
#define CP16(dst, src) asm volatile("cp.async.cg.shared.global [%0], [%1], 16;" :: "r"(dst), "l"(src))
#define CPCOMMIT() asm volatile("cp.async.commit_group;" ::: "memory")
#define CPWAIT1() asm volatile("cp.async.wait_group 1;" ::: "memory")

__device__ __forceinline__ uint32_t smem_u32(const void* p) {
    uint32_t a;
    asm("{ .reg .u64 t; cvta.to.shared.u64 t, %1; cvt.u32.u64 %0, t; }" : "=r"(a) : "l"(p));
    return a;
}
__device__ __forceinline__ uint32_t cvt_tf32(float f) {
    uint32_t r;
    asm("cvt.rna.tf32.f32 %0, %1;" : "=r"(r) : "f"(f));
    return r;
}
__device__ __forceinline__ void ldsm4(uint32_t& r0, uint32_t& r1, uint32_t& r2, uint32_t& r3,
                                      uint32_t a) {
    asm volatile("ldmatrix.sync.aligned.m8n8.x4.shared.b16 {%0,%1,%2,%3}, [%4];"
                 : "=r"(r0), "=r"(r1), "=r"(r2), "=r"(r3) : "r"(a));
}
// ldmatrix reg order vs tf32 m16n8k8 A fragment: pass a[0], a[2], a[1], a[3].
__device__ __forceinline__ void mma8(float* c, const uint32_t* a, const uint32_t* b) {
    asm volatile(
        "mma.sync.aligned.m16n8k8.row.col.f32.tf32.tf32.f32 "
        "{%0,%1,%2,%3}, {%4,%5,%6,%7}, {%8,%9}, {%0,%1,%2,%3};"
        : "+f"(c[0]), "+f"(c[1]), "+f"(c[2]), "+f"(c[3])
        : "r"(a[0]), "r"(a[2]), "r"(a[1]), "r"(a[3]), "r"(b[0]), "r"(b[1]));
}

// ---------------------------------------------------------------------------
// prep: transpose weights to K-major [N][K]; concat q|k weights + biases.
// ---------------------------------------------------------------------------
__global__ void prep_kernel(const float* __restrict__ wq, const float* __restrict__ bq,
                            const float* __restrict__ wk, const float* __restrict__ bk,
                            const float* __restrict__ wv, const float* __restrict__ wm)
{
    int idx = blockIdx.x * blockDim.x + threadIdx.x;
    for (int i = idx; i < 512 * 512; i += gridDim.x * blockDim.x) {
        int c = i >> 9, k = i & 511;
        g_WvT[i] = wv[k * 512 + c];
        g_WmT[i] = wm[k * 512 + c];
        if (c < 64) {
            g_Wqk[c * 512 + k]        = wq[k * 64 + c];
            g_Wqk[(64 + c) * 512 + k] = wk[k * 64 + c];
        }
    }
    if (idx < 64) { g_bqk[idx] = bq[idx]; g_bqk[64 + idx] = bk[idx]; }
}

// ---------------------------------------------------------------------------
// cp.async stager for one 128x32 A chunk + 128x32 B chunk into ring buffer buf.
// A buffers @ buf*16K; B buffers @ 48K + buf*16K  (3 stages, 96 KB total).
// ---------------------------------------------------------------------------
__device__ __forceinline__ void stage_ab(uint32_t sbase, int buf,
                                         const float* Ab, int lda,
                                         const float* Bb, int ldb,
                                         int k0, int tid)
{
    uint32_t aoff = sbase + (uint32_t)buf * 16384u;
    uint32_t boff = sbase + 49152u + (uint32_t)buf * 16384u;
#pragma unroll
    for (int i = 0; i < 4; i++) {
        int idx = tid + i * 256, row = idx >> 3, seg = idx & 7;
        CP16(aoff + SWZ(row * 128 + seg * 16), Ab + (size_t)row * lda + k0 + seg * 4);
        CP16(boff + SWZ(row * 128 + seg * 16), Bb + (size_t)row * ldb + k0 + seg * 4);
    }
}

// ---------------------------------------------------------------------------
// Generic tf32 mma.sync GEMM: C[z][m][n] = sum_k A[z][m][k]*B[z][n][k] (+biases)
// 128x128 block tile, 8 warps (2x4), warp tile 64x32, K chunks of 32.
// 3-stage cp.async ring, single __syncthreads per chunk.
// ---------------------------------------------------------------------------
__global__ __launch_bounds__(256, 2) void tc_gemm_kernel(
    const float* __restrict__ A, int lda, int sAz,
    const float* __restrict__ Bm, int ldb, int sBz,
    float* __restrict__ Cm, int ldc, int sCz,
    int Ktot, const float* __restrict__ colBias, const float* __restrict__ rowBias)
{
    extern __shared__ char dsm[];
    const uint32_t sbase = smem_u32(dsm);

    const int tid = threadIdx.x, wid = tid >> 5, lane = tid & 31;
    const int m0w = (wid >> 2) * 64, n0w = (wid & 3) * 32;
    const int z = blockIdx.z;
    const float* Ab = A + (size_t)z * sAz + (size_t)(blockIdx.x * BLKM) * lda;
    const float* Bb = Bm + (size_t)z * sBz + (size_t)(blockIdx.y * BLKN) * ldb;

    const int frow = (lane & 7) + ((lane >> 4) & 1) * 8;
    const int fseg = ((lane >> 3) & 1) * 16;

    float acc[4][4][4] = {};
    const int nch = Ktot / BK;

    stage_ab(sbase, 0, Ab, lda, Bb, ldb, 0, tid);
    CPCOMMIT();
    stage_ab(sbase, 1, Ab, lda, Bb, ldb, BK, tid);
    CPCOMMIT();

    int buf = 0;
    for (int kc = 0; kc < nch; kc++) {
        CPWAIT1();
        __syncthreads();

        const uint32_t sA = sbase + (uint32_t)buf * 16384u;
        const uint32_t sB = sbase + 49152u + (uint32_t)buf * 16384u;
#pragma unroll
        for (int ks = 0; ks < 4; ks++) {
            uint32_t af[4][4], bf[2][4];
#pragma unroll
            for (int mf = 0; mf < 4; mf++)
                ldsm4(af[mf][0], af[mf][1], af[mf][2], af[mf][3],
                      sA + SWZ((m0w + mf * 16 + frow) * 128 + ks * 32 + fseg));
#pragma unroll
            for (int bi = 0; bi < 2; bi++)
                ldsm4(bf[bi][0], bf[bi][1], bf[bi][2], bf[bi][3],
                      sB + SWZ((n0w + bi * 16 + frow) * 128 + ks * 32 + fseg));
#pragma unroll
            for (int mf = 0; mf < 4; mf++)
#pragma unroll
                for (int nf = 0; nf < 4; nf++)
                    mma8(acc[mf][nf], af[mf], &bf[nf >> 1][(nf & 1) * 2]);
        }

        if (kc + 2 < nch) {
            int nb = buf + 2; if (nb >= 3) nb -= 3;
            stage_ab(sbase, nb, Ab, lda, Bb, ldb, (kc + 2) * BK, tid);
        }
        CPCOMMIT();
        if (++buf == 3) buf = 0;
    }

    // epilogue: c0/c1 at (row, col..col+1), c2/c3 at (row+8, ...)
    const int lr = lane >> 2, lc = (lane & 3) * 2;
#pragma unroll
    for (int mf = 0; mf < 4; mf++)
#pragma unroll
        for (int nf = 0; nf < 4; nf++) {
            int row = blockIdx.x * BLKM + m0w + mf * 16 + lr;
            int col = blockIdx.y * BLKN + n0w + nf * 8 + lc;
            float cb0 = 0.f, cb1 = 0.f;
            if (colBias) { cb0 = colBias[col]; cb1 = colBias[col + 1]; }
            float rb0 = rowBias ? rowBias[row] : 0.f;
            float rb1 = rowBias ? rowBias[row + 8] : 0.f;
            float* p0 = Cm + (size_t)z * sCz + (size_t)row * ldc + col;
            float2 o0 = {acc[mf][nf][0] + cb0 + rb0, acc[mf][nf][1] + cb1 + rb0};
            float2 o1 = {acc[mf][nf][2] + cb0 + rb1, acc[mf][nf][3] + cb1 + rb1};
            *(float2*)p0 = o0;
            *(float2*)(p0 + (size_t)8 * ldc) = o1;
        }
}

// ---------------------------------------------------------------------------
// Scores + g-fold: block = 32 queries x 256 keys, 8 warps (warp n0 = wid*32).
// Q (32x64, rna-rounded) resident in smem; key chunks (256x32) in a 3-stage
// cp.async ring across the 16 (g,kc) chunks; single sync per chunk.
// acc accumulates both kc of a g; fold += expf(acc) after kc==1.
// Dyn smem: Q kc0 @0, Q kc1 @4K; key bufs @8K + buf*32K  (104 KB).
// ---------------------------------------------------------------------------
__global__ __launch_bounds__(256, 2) void scores_tc_kernel(
    const float* __restrict__ QK, float* __restrict__ Wt)
{
    extern __shared__ char dsm[];
    const uint32_t sbase = smem_u32(dsm);

    const int tid = threadIdx.x, wid = tid >> 5, lane = tid & 31;
    const int n0w = wid * 32;
    const int b = blockIdx.y;
    const int qbase = b * NB + blockIdx.x * 32;

    const int frow = (lane & 7) + ((lane >> 4) & 1) * 8;
    const int fseg = ((lane >> 3) & 1) * 16;

    // stage Q (rna-rounded; register path, conversion is free)
#pragma unroll
    for (int i = 0; i < 2; i++) {
        int idx = tid + i * 256;
        int row = idx >> 4, seg = idx & 15;            // row 0..31, k = seg*4
        float4 v = *(const float4*)(QK + (size_t)(qbase + row) * 128 + seg * 4);
        uint4 t = {cvt_tf32(v.x), cvt_tf32(v.y), cvt_tf32(v.z), cvt_tf32(v.w)};
        uint32_t off = (uint32_t)((seg >> 3) * 4096) + SWZ(row * 128 + (seg & 7) * 16);
        *(uint4*)(dsm + off) = t;
    }

    // key chunk stager: chunk t -> g=t>>1, kc=t&1; 256 rows x 32 k, ring buf
    const float* kb0 = QK + (size_t)b * NB * 128 + 64;
#define STAGE_KEYS(t, bufi)                                                    \
    do {                                                                       \
        const float* kb = kb0 + (size_t)((t) >> 1) * 256 * 128 + ((t) & 1) * 32; \
        uint32_t koff = sbase + 8192u + (uint32_t)(bufi) * 32768u;             \
        _Pragma("unroll")                                                      \
        for (int i = 0; i < 8; i++) {                                          \
            int idx = tid + i * 256, row = idx >> 3, seg = idx & 7;            \
            CP16(koff + SWZ(row * 128 + seg * 16), kb + (size_t)row * 128 + seg * 4); \
        }                                                                      \
    } while (0)

    float fold[2][4][4] = {};
    float acc[2][4][4];

    STAGE_KEYS(0, 0);
    CPCOMMIT();
    STAGE_KEYS(1, 1);
    CPCOMMIT();

    int buf = 0;
    for (int t = 0; t < 16; t++) {
        CPWAIT1();
        __syncthreads();

        const int kc = t & 1;
        if (kc == 0) {
#pragma unroll
            for (int mf = 0; mf < 2; mf++)
#pragma unroll
                for (int nf = 0; nf < 4; nf++)
#pragma unroll
                    for (int r = 0; r < 4; r++) acc[mf][nf][r] = 0.f;
        }
        const uint32_t sQ = sbase + (uint32_t)kc * 4096u;
        const uint32_t sK = sbase + 8192u + (uint32_t)buf * 32768u;
#pragma unroll
        for (int ks = 0; ks < 4; ks++) {
            uint32_t af[2][4], bf[2][4];
#pragma unroll
            for (int mf = 0; mf < 2; mf++)
                ldsm4(af[mf][0], af[mf][1], af[mf][2], af[mf][3],
                      sQ + SWZ((mf * 16 + frow) * 128 + ks * 32 + fseg));
#pragma unroll
            for (int bi = 0; bi < 2; bi++)
                ldsm4(bf[bi][0], bf[bi][1], bf[bi][2], bf[bi][3],
                      sK + SWZ((n0w + bi * 16 + frow) * 128 + ks * 32 + fseg));
#pragma unroll
            for (int mf = 0; mf < 2; mf++)
#pragma unroll
                for (int nf = 0; nf < 4; nf++)
                    mma8(acc[mf][nf], af[mf], &bf[nf >> 1][(nf & 1) * 2]);
        }

        if (t + 2 < 16) {
            int nb = buf + 2; if (nb >= 3) nb -= 3;
            STAGE_KEYS(t + 2, nb);
        }
        CPCOMMIT();

        if (kc == 1) {
#pragma unroll
            for (int mf = 0; mf < 2; mf++)
#pragma unroll
                for (int nf = 0; nf < 4; nf++)
#pragma unroll
                    for (int r = 0; r < 4; r++)
                        fold[mf][nf][r] += __expf(acc[mf][nf][r]);
        }
        if (++buf == 3) buf = 0;
    }
#undef STAGE_KEYS

    const int lr = lane >> 2, lc = (lane & 3) * 2;
#pragma unroll
    for (int mf = 0; mf < 2; mf++)
#pragma unroll
        for (int nf = 0; nf < 4; nf++) {
            int row = qbase + mf * 16 + lr;
            int col = n0w + nf * 8 + lc;
            float2 o0 = {fold[mf][nf][0], fold[mf][nf][1]};
            float2 o1 = {fold[mf][nf][2], fold[mf][nf][3]};
            *(float2*)(Wt + (size_t)row * 256 + col) = o0;
            *(float2*)(Wt + (size_t)(row + 8) * 256 + col) = o1;
        }
}

// ---------------------------------------------------------------------------
// Epilogue 1: y1 = LN(attnU/Z + x). One warp per row.
// ---------------------------------------------------------------------------
__global__ __launch_bounds__(256) void attn_ep_kernel(
    const float* __restrict__ Wt, const float* __restrict__ attn,
    const float* __restrict__ x, const float* __restrict__ g1,
    const float* __restrict__ b1, float* __restrict__ Y1)
{
    const int lane = threadIdx.x & 31;
    const size_t row = (size_t)blockIdx.x * 8 + (threadIdx.x >> 5);
    float z = 0.f;
#pragma unroll
    for (int j = 0; j < 8; j++) z += Wt[row * 256 + j * 32 + lane];
#pragma unroll
    for (int o = 16; o; o >>= 1) z += __shfl_xor_sync(0xffffffffu, z, o);
    float invz = 1.f / z;

    float vals[16], s1 = 0.f, s2 = 0.f;
#pragma unroll
    for (int j = 0; j < 16; j++) {
        int c = j * 32 + lane;
        float v = attn[row * 512 + c] * invz + x[row * 512 + c];
        vals[j] = v; s1 += v; s2 += v * v;
    }
#pragma unroll
    for (int o = 16; o; o >>= 1) {
        s1 += __shfl_xor_sync(0xffffffffu, s1, o);
        s2 += __shfl_xor_sync(0xffffffffu, s2, o);
    }
    float mean = s1 * (1.f / 512.f);
    float var = s2 * (1.f / 512.f) - mean * mean;
    float rstd = rsqrtf(var + 1e-3f);
#pragma unroll
    for (int j = 0; j < 16; j++) {
        int c = j * 32 + lane;
        Y1[row * 512 + c] = (vals[j] - mean) * rstd * g1[c] + b1[c];
    }
}

// ---------------------------------------------------------------------------
// Epilogue 2: out = LN(y1 + relu(mlp))   (bm already added in GEMM epilogue)
// ---------------------------------------------------------------------------
__global__ __launch_bounds__(256) void mlp_ep_kernel(
    const float* __restrict__ Y1, const float* __restrict__ mlp,
    const float* __restrict__ g2, const float* __restrict__ b2,
    float* __restrict__ Out)
{
    const int lane = threadIdx.x & 31;
    const size_t row = (size_t)blockIdx.x * 8 + (threadIdx.x >> 5);

    float vals[16], s1 = 0.f, s2 = 0.f;
#pragma unroll
    for (int j = 0; j < 16; j++) {
        int c = j * 32 + lane;
        float v = Y1[row * 512 + c] + fmaxf(mlp[row * 512 + c], 0.f);
        vals[j] = v; s1 += v; s2 += v * v;
    }
#pragma unroll
    for (int o = 16; o; o >>= 1) {
        s1 += __shfl_xor_sync(0xffffffffu, s1, o);
        s2 += __shfl_xor_sync(0xffffffffu, s2, o);
    }
    float mean = s1 * (1.f / 512.f);
    float var = s2 * (1.f / 512.f) - mean * mean;
    float rstd = rsqrtf(var + 1e-3f);
#pragma unroll
    for (int j = 0; j < 16; j++) {
        int c = j * 32 + lane;
        Out[row * 512 + c] = (vals[j] - mean) * rstd * g2[c] + b2[c];
    }
}

// ---------------------------------------------------------------------------
extern "C" void kernel_launch(void* const* d_in, const int* in_sizes, int n_in,
                              void* d_out, int out_size)
{
    const float* x  = (const float*)d_in[0];
    const float* wq = (const float*)d_in[1];
    const float* bq = (const float*)d_in[2];
    const float* wk = (const float*)d_in[3];
    const float* bk = (const float*)d_in[4];
    const float* wv = (const float*)d_in[5];
    const float* bv = (const float*)d_in[6];
    const float* wm = (const float*)d_in[7];
    const float* bm = (const float*)d_in[8];
    const float* g1 = (const float*)d_in[9];
    const float* b1 = (const float*)d_in[10];
    const float* g2 = (const float*)d_in[11];
    const float* b2 = (const float*)d_in[12];
    float* out = (float*)d_out;

    float *Wqkp, *bqkp, *WvTp, *WmTp, *QKp, *Vtp, *Wtp, *attnp, *Y1p, *mlpp;
    cudaGetSymbolAddress((void**)&Wqkp, g_Wqk);
    cudaGetSymbolAddress((void**)&bqkp, g_bqk);
    cudaGetSymbolAddress((void**)&WvTp, g_WvT);
    cudaGetSymbolAddress((void**)&WmTp, g_WmT);
    cudaGetSymbolAddress((void**)&QKp,  g_QK);
    cudaGetSymbolAddress((void**)&Vtp,  g_Vt);
    cudaGetSymbolAddress((void**)&Wtp,  g_Wt);
    cudaGetSymbolAddress((void**)&attnp, g_attn);
    cudaGetSymbolAddress((void**)&Y1p,  g_Y1);
    cudaGetSymbolAddress((void**)&mlpp, g_mlp);

    const int GEMM_SMEM = 98304;                 // 3 x (16K A + 16K B)
    const int SC_SMEM   = 8192 + 3 * 32768;      // Q + 3 key stages = 104 KB
    cudaFuncSetAttribute(tc_gemm_kernel, cudaFuncAttributeMaxDynamicSharedMemorySize, GEMM_SMEM);
    cudaFuncSetAttribute(scores_tc_kernel, cudaFuncAttributeMaxDynamicSharedMemorySize, SC_SMEM);

    // 0) weight prep (transposes + q|k concat)
    prep_kernel<<<256, 256>>>(wq, bq, wk, bk, wv, wm);

    // 1) QK projection: [8192,128] = x . Wqk^T   (+bqk per col)
    tc_gemm_kernel<<<dim3(64, 1, 1), 256, GEMM_SMEM>>>(
        x, 512, 0, Wqkp, 512, 0, QKp, 128, 0, 512, bqkp, nullptr);

    // 2) V transposed: Vt[c][pos] = WvT[c][:] . x[pos][:]   (+bv per row=c)
    tc_gemm_kernel<<<dim3(4, 64, 1), 256, GEMM_SMEM>>>(
        WvTp, 512, 0, x, 512, 0, Vtp, NPOS, 0, 512, nullptr, bv);

    // 3) scores + g-fold -> unnormalized Wt [8192 x 256]
    scores_tc_kernel<<<dim3(64, 4, 1), 256, SC_SMEM>>>(QKp, Wtp);

    // 4) attnU[z] = Wt[z] @ Vt[:, z*256:+256]^T  per (b,d) slice z (32 slices)
    tc_gemm_kernel<<<dim3(2, 4, 32), 256, GEMM_SMEM>>>(
        Wtp, 256, 65536, Vtp, NPOS, 256, attnp, 512, 131072, 256, nullptr, nullptr);

    // 5) y1 = LN(attnU/Z + x)
    attn_ep_kernel<<<NPOS / 8, 256>>>(Wtp, attnp, x, g1, b1, Y1p);

    // 6) mlp = y1 @ wm + bm
    tc_gemm_kernel<<<dim3(64, 4, 1), 256, GEMM_SMEM>>>(
        Y1p, 512, 0, WmTp, 512, 0, mlpp, 512, 0, 512, bm, nullptr);

    // 7) out = LN(y1 + relu(mlp))
    mlp_ep_kernel<<<NPOS / 8, 256>>>(Y1p, mlpp, g2, b2, out);
}

// round 14
// speedup vs baseline: 4.6907x; 1.0823x over previous
#include <cuda_runtime.h>
#include <cuda_fp16.h>
#include <cstdint>

#define B_ 4
#define D_ 8
#define F_ 256
#define C_ 512
#define NPOS 8192
#define NB 2048
#define BLKM 128
#define BLKN 128
#define BK 64

// ---------------- scratch (static device allocations only) ----------------
__device__ __half g_xh[NPOS * 512];      // x in fp16
__device__ __half g_Wqk_h[128 * 512];    // [n = q|k dim][k] K-major fp16
__device__ float  g_bqk[128];
__device__ __half g_WvT_h[512 * 512];    // wv^T fp16
__device__ __half g_WmT_h[512 * 512];    // wm^T fp16
__device__ __half g_QK_h[NPOS * 128];    // [pos][ q(64) | k(64) ] fp16
__device__ __half g_Vt_h[512 * NPOS];    // V transposed [c][pos] fp16
__device__ float  g_Wt[NPOS * 256];      // unnormalized folded attn weights (for Z)
__device__ __half g_Wt_h[NPOS * 256];    // same, scaled by 1/64, fp16
__device__ float  g_attn[NPOS * 512];    // Wt_h @ V (scaled by 1/64)
__device__ float  g_Y1[NPOS * 512];
__device__ __half g_Y1_h[NPOS * 512];
__device__ float  g_mlp[NPOS * 512];

// ---------------- helpers ----------------
#define SWZ(x) ((x) ^ (((x) >> 3) & 0x70))
#define CP16(dst, src) asm volatile("cp.async.cg.shared.global [%0], [%1], 16;" :: "r"(dst), "l"(src))
#define CPCOMMIT() asm volatile("cp.async.commit_group;" ::: "memory")
#define CPWAIT1() asm volatile("cp.async.wait_group 1;" ::: "memory")

__device__ __forceinline__ uint32_t smem_u32(const void* p) {
    uint32_t a;
    asm("{ .reg .u64 t; cvta.to.shared.u64 t, %1; cvt.u32.u64 %0, t; }" : "=r"(a) : "l"(p));
    return a;
}
__device__ __forceinline__ void ldsm4(uint32_t& r0, uint32_t& r1, uint32_t& r2, uint32_t& r3,
                                      uint32_t a) {
    asm volatile("ldmatrix.sync.aligned.m8n8.x4.shared.b16 {%0,%1,%2,%3}, [%4];"
                 : "=r"(r0), "=r"(r1), "=r"(r2), "=r"(r3) : "r"(a));
}
// fp16 m16n8k16, fp32 accum. With frow=(lane&7)+((lane>>3)&1)*8, fseg=(lane>>4)*16,
// ldsm.x4 over A (16 rows x 16 k) returns {a0,a1,a2,a3} in natural order.
__device__ __forceinline__ void mma16(float* c, const uint32_t* a, uint32_t b0, uint32_t b1) {
    asm volatile(
        "mma.sync.aligned.m16n8k16.row.col.f32.f16.f16.f32 "
        "{%0,%1,%2,%3}, {%4,%5,%6,%7}, {%8,%9}, {%0,%1,%2,%3};"
        : "+f"(c[0]), "+f"(c[1]), "+f"(c[2]), "+f"(c[3])
        : "r"(a[0]), "r"(a[1]), "r"(a[2]), "r"(a[3]), "r"(b0), "r"(b1));
}

// ---------------------------------------------------------------------------
// prep: fp16 conversions — x, and weights transposed to K-major [N][K].
// ---------------------------------------------------------------------------
__global__ void prep_kernel(const float* __restrict__ x,
                            const float* __restrict__ wq, const float* __restrict__ bq,
                            const float* __restrict__ wk, const float* __restrict__ bk,
                            const float* __restrict__ wv, const float* __restrict__ wm)
{
    int idx = blockIdx.x * blockDim.x + threadIdx.x;
    for (int i = idx; i < NPOS * 512; i += gridDim.x * blockDim.x) {
        g_xh[i] = __float2half_rn(x[i]);
        if (i < 512 * 512) {
            int c = i >> 9, k = i & 511;
            g_WvT_h[i] = __float2half_rn(wv[k * 512 + c]);
            g_WmT_h[i] = __float2half_rn(wm[k * 512 + c]);
            if (c < 64) {
                g_Wqk_h[c * 512 + k]        = __float2half_rn(wq[k * 64 + c]);
                g_Wqk_h[(64 + c) * 512 + k] = __float2half_rn(wk[k * 64 + c]);
            }
        }
    }
    if (idx < 64) { g_bqk[idx] = bq[idx]; g_bqk[64 + idx] = bk[idx]; }
}

// ---------------------------------------------------------------------------
// cp.async stager: one 128x64 fp16 A chunk + B chunk (row = 128 B) into ring
// buffer buf. A @ buf*16K; B @ 48K + buf*16K (3 stages, 96 KB).
// ---------------------------------------------------------------------------
__device__ __forceinline__ void stage_ab(uint32_t sbase, int buf,
                                         const __half* Ab, int lda,
                                         const __half* Bb, int ldb,
                                         int k0, int tid)
{
    uint32_t aoff = sbase + (uint32_t)buf * 16384u;
    uint32_t boff = sbase + 49152u + (uint32_t)buf * 16384u;
#pragma unroll
    for (int i = 0; i < 4; i++) {
        int idx = tid + i * 256, row = idx >> 3, seg = idx & 7;
        CP16(aoff + SWZ(row * 128 + seg * 16), Ab + (size_t)row * lda + k0 + seg * 8);
        CP16(boff + SWZ(row * 128 + seg * 16), Bb + (size_t)row * ldb + k0 + seg * 8);
    }
}

// ---------------------------------------------------------------------------
// fp16 mma.sync GEMM: C[z][m][n] = sum_k A[z][m][k]*B[z][n][k] (+biases)
// Both operands K-major fp16. 128x128 block tile, 8 warps (2x4), warp 64x32,
// K chunks of 64 (4 x k16 steps). 3-stage cp.async ring, 1 sync per chunk.
// Output: fp32 to Cf and/or fp16 to Ch (whichever is non-null).
// ---------------------------------------------------------------------------
__global__ __launch_bounds__(256, 2) void hgemm_kernel(
    const __half* __restrict__ A, int lda, int sAz,
    const __half* __restrict__ Bm, int ldb, int sBz,
    float* __restrict__ Cf, __half* __restrict__ Ch, int ldc, int sCz,
    int Ktot, const float* __restrict__ colBias, const float* __restrict__ rowBias)
{
    extern __shared__ char dsm[];
    const uint32_t sbase = smem_u32(dsm);

    const int tid = threadIdx.x, wid = tid >> 5, lane = tid & 31;
    const int m0w = (wid >> 2) * 64, n0w = (wid & 3) * 32;
    const int z = blockIdx.z;
    const __half* Ab = A + (size_t)z * sAz + (size_t)(blockIdx.x * BLKM) * lda;
    const __half* Bb = Bm + (size_t)z * sBz + (size_t)(blockIdx.y * BLKN) * ldb;

    const int frow = (lane & 7) + ((lane >> 3) & 1) * 8;
    const int fseg = (lane >> 4) * 16;

    float acc[4][4][4] = {};
    const int nch = Ktot / BK;

    stage_ab(sbase, 0, Ab, lda, Bb, ldb, 0, tid);
    CPCOMMIT();
    if (nch > 1) stage_ab(sbase, 1, Ab, lda, Bb, ldb, BK, tid);
    CPCOMMIT();

    int buf = 0;
    for (int kc = 0; kc < nch; kc++) {
        CPWAIT1();
        __syncthreads();

        const uint32_t sA = sbase + (uint32_t)buf * 16384u;
        const uint32_t sB = sbase + 49152u + (uint32_t)buf * 16384u;
#pragma unroll
        for (int ks = 0; ks < 4; ks++) {              // k16 steps
            uint32_t af[4][4], bf[2][4];
#pragma unroll
            for (int mf = 0; mf < 4; mf++)
                ldsm4(af[mf][0], af[mf][1], af[mf][2], af[mf][3],
                      sA + SWZ((m0w + mf * 16 + frow) * 128 + ks * 32 + fseg));
#pragma unroll
            for (int bi = 0; bi < 2; bi++)
                ldsm4(bf[bi][0], bf[bi][1], bf[bi][2], bf[bi][3],
                      sB + SWZ((n0w + bi * 16 + frow) * 128 + ks * 32 + fseg));
#pragma unroll
            for (int mf = 0; mf < 4; mf++)
#pragma unroll
                for (int nf = 0; nf < 4; nf++)        // nf -> n0w + nf*8
                    mma16(acc[mf][nf], af[mf],
                          bf[nf >> 1][nf & 1], bf[nf >> 1][(nf & 1) + 2]);
        }

        if (kc + 2 < nch) {
            int nb = buf + 2; if (nb >= 3) nb -= 3;
            stage_ab(sbase, nb, Ab, lda, Bb, ldb, (kc + 2) * BK, tid);
        }
        CPCOMMIT();
        if (++buf == 3) buf = 0;
    }

    // epilogue: c0/c1 at (row, col..col+1), c2/c3 at (row+8, ...)
    const int lr = lane >> 2, lc = (lane & 3) * 2;
#pragma unroll
    for (int mf = 0; mf < 4; mf++)
#pragma unroll
        for (int nf = 0; nf < 4; nf++) {
            int row = blockIdx.x * BLKM + m0w + mf * 16 + lr;
            int col = blockIdx.y * BLKN + n0w + nf * 8 + lc;
            float cb0 = 0.f, cb1 = 0.f;
            if (colBias) { cb0 = colBias[col]; cb1 = colBias[col + 1]; }
            float rb0 = rowBias ? rowBias[row] : 0.f;
            float rb1 = rowBias ? rowBias[row + 8] : 0.f;
            float v00 = acc[mf][nf][0] + cb0 + rb0, v01 = acc[mf][nf][1] + cb1 + rb0;
            float v10 = acc[mf][nf][2] + cb0 + rb1, v11 = acc[mf][nf][3] + cb1 + rb1;
            size_t p = (size_t)z * sCz + (size_t)row * ldc + col;
            if (Cf) {
                *(float2*)(Cf + p) = make_float2(v00, v01);
                *(float2*)(Cf + p + (size_t)8 * ldc) = make_float2(v10, v11);
            }
            if (Ch) {
                *(__half2*)(Ch + p) = __floats2half2_rn(v00, v01);
                *(__half2*)(Ch + p + (size_t)8 * ldc) = __floats2half2_rn(v10, v11);
            }
        }
}

// ---------------------------------------------------------------------------
// Scores + g-fold: block = 32 queries x 256 keys, 8 warps (warp n0 = wid*32).
// Q (32x64 fp16) resident; per g one key chunk 256x64 fp16 (32 KB) in a
// 3-stage ring; 4 k16 steps per chunk; fold += expf(acc) per g.
// Writes Wt fp32 (for Z) and Wt_h = fold/64 fp16 (attn GEMM operand).
// Dyn smem: Q @0 (4K); key bufs @4K + buf*32K  (100 KB).
// ---------------------------------------------------------------------------
__global__ __launch_bounds__(256, 2) void scores_h_kernel(
    const __half* __restrict__ QK, float* __restrict__ Wt, __half* __restrict__ Wth)
{
    extern __shared__ char dsm[];
    const uint32_t sbase = smem_u32(dsm);

    const int tid = threadIdx.x, wid = tid >> 5, lane = tid & 31;
    const int n0w = wid * 32;
    const int b = blockIdx.y;
    const int qbase = b * NB + blockIdx.x * 32;

    const int frow = (lane & 7) + ((lane >> 3) & 1) * 8;
    const int fseg = (lane >> 4) * 16;

    const __half* kb0 = QK + (size_t)b * NB * 128 + 64;
#define STAGE_KEYS(g, bufi)                                                    \
    do {                                                                       \
        const __half* kb = kb0 + (size_t)(g) * 256 * 128;                      \
        uint32_t koff = sbase + 4096u + (uint32_t)(bufi) * 32768u;             \
        _Pragma("unroll")                                                      \
        for (int i = 0; i < 8; i++) {                                          \
            int idx = tid + i * 256, row = idx >> 3, seg = idx & 7;            \
            CP16(koff + SWZ(row * 128 + seg * 16), kb + (size_t)row * 128 + seg * 8); \
        }                                                                      \
    } while (0)

    // stage Q (32 rows x 64 fp16 = 256 x 16B segs, one per thread) + keys g0
    {
        int row = tid >> 3, seg = tid & 7;
        CP16(sbase + SWZ(row * 128 + seg * 16),
             QK + (size_t)(qbase + row) * 128 + seg * 8);
    }
    STAGE_KEYS(0, 0);
    CPCOMMIT();
    STAGE_KEYS(1, 1);
    CPCOMMIT();

    float fold[2][4][4] = {};
    int buf = 0;
    for (int g = 0; g < 8; g++) {
        CPWAIT1();
        __syncthreads();

        float acc[2][4][4] = {};
        const uint32_t sK = sbase + 4096u + (uint32_t)buf * 32768u;
#pragma unroll
        for (int ks = 0; ks < 4; ks++) {
            uint32_t af[2][4], bf[2][4];
#pragma unroll
            for (int mf = 0; mf < 2; mf++)
                ldsm4(af[mf][0], af[mf][1], af[mf][2], af[mf][3],
                      sbase + SWZ((mf * 16 + frow) * 128 + ks * 32 + fseg));
#pragma unroll
            for (int bi = 0; bi < 2; bi++)
                ldsm4(bf[bi][0], bf[bi][1], bf[bi][2], bf[bi][3],
                      sK + SWZ((n0w + bi * 16 + frow) * 128 + ks * 32 + fseg));
#pragma unroll
            for (int mf = 0; mf < 2; mf++)
#pragma unroll
                for (int nf = 0; nf < 4; nf++)
                    mma16(acc[mf][nf], af[mf],
                          bf[nf >> 1][nf & 1], bf[nf >> 1][(nf & 1) + 2]);
        }

        if (g + 2 < 8) {
            int nb = buf + 2; if (nb >= 3) nb -= 3;
            STAGE_KEYS(g + 2, nb);
        }
        CPCOMMIT();

#pragma unroll
        for (int mf = 0; mf < 2; mf++)
#pragma unroll
            for (int nf = 0; nf < 4; nf++)
#pragma unroll
                for (int r = 0; r < 4; r++)
                    fold[mf][nf][r] += __expf(acc[mf][nf][r]);
        if (++buf == 3) buf = 0;
    }
#undef STAGE_KEYS

    const int lr = lane >> 2, lc = (lane & 3) * 2;
#pragma unroll
    for (int mf = 0; mf < 2; mf++)
#pragma unroll
        for (int nf = 0; nf < 4; nf++) {
            int row = qbase + mf * 16 + lr;
            int col = n0w + nf * 8 + lc;
            float f00 = fold[mf][nf][0], f01 = fold[mf][nf][1];
            float f10 = fold[mf][nf][2], f11 = fold[mf][nf][3];
            *(float2*)(Wt + (size_t)row * 256 + col) = make_float2(f00, f01);
            *(float2*)(Wt + (size_t)(row + 8) * 256 + col) = make_float2(f10, f11);
            const float s = 1.f / 64.f;   // overflow guard; compensated in attn_ep
            *(__half2*)(Wth + (size_t)row * 256 + col) = __floats2half2_rn(f00 * s, f01 * s);
            *(__half2*)(Wth + (size_t)(row + 8) * 256 + col) = __floats2half2_rn(f10 * s, f11 * s);
        }
}

// ---------------------------------------------------------------------------
// Epilogue 1: y1 = LN(attnU*64/Z + x). One warp per row. Writes Y1 + Y1_h.
// ---------------------------------------------------------------------------
__global__ __launch_bounds__(256) void attn_ep_kernel(
    const float* __restrict__ Wt, const float* __restrict__ attn,
    const float* __restrict__ x, const float* __restrict__ g1,
    const float* __restrict__ b1, float* __restrict__ Y1, __half* __restrict__ Y1h)
{
    const int lane = threadIdx.x & 31;
    const size_t row = (size_t)blockIdx.x * 8 + (threadIdx.x >> 5);
    float z = 0.f;
#pragma unroll
    for (int j = 0; j < 8; j++) z += Wt[row * 256 + j * 32 + lane];
#pragma unroll
    for (int o = 16; o; o >>= 1) z += __shfl_xor_sync(0xffffffffu, z, o);
    float invz = 64.f / z;    // 64 compensates the 1/64 scale on Wt_h

    float vals[16], s1 = 0.f, s2 = 0.f;
#pragma unroll
    for (int j = 0; j < 16; j++) {
        int c = j * 32 + lane;
        float v = attn[row * 512 + c] * invz + x[row * 512 + c];
        vals[j] = v; s1 += v; s2 += v * v;
    }
#pragma unroll
    for (int o = 16; o; o >>= 1) {
        s1 += __shfl_xor_sync(0xffffffffu, s1, o);
        s2 += __shfl_xor_sync(0xffffffffu, s2, o);
    }
    float mean = s1 * (1.f / 512.f);
    float var = s2 * (1.f / 512.f) - mean * mean;
    float rstd = rsqrtf(var + 1e-3f);
#pragma unroll
    for (int j = 0; j < 16; j++) {
        int c = j * 32 + lane;
        float y = (vals[j] - mean) * rstd * g1[c] + b1[c];
        Y1[row * 512 + c] = y;
        Y1h[row * 512 + c] = __float2half_rn(y);
    }
}

// ---------------------------------------------------------------------------
// Epilogue 2: out = LN(y1 + relu(mlp))   (bm already added in GEMM epilogue)
// ---------------------------------------------------------------------------
__global__ __launch_bounds__(256) void mlp_ep_kernel(
    const float* __restrict__ Y1, const float* __restrict__ mlp,
    const float* __restrict__ g2, const float* __restrict__ b2,
    float* __restrict__ Out)
{
    const int lane = threadIdx.x & 31;
    const size_t row = (size_t)blockIdx.x * 8 + (threadIdx.x >> 5);

    float vals[16], s1 = 0.f, s2 = 0.f;
#pragma unroll
    for (int j = 0; j < 16; j++) {
        int c = j * 32 + lane;
        float v = Y1[row * 512 + c] + fmaxf(mlp[row * 512 + c], 0.f);
        vals[j] = v; s1 += v; s2 += v * v;
    }
#pragma unroll
    for (int o = 16; o; o >>= 1) {
        s1 += __shfl_xor_sync(0xffffffffu, s1, o);
        s2 += __shfl_xor_sync(0xffffffffu, s2, o);
    }
    float mean = s1 * (1.f / 512.f);
    float var = s2 * (1.f / 512.f) - mean * mean;
    float rstd = rsqrtf(var + 1e-3f);
#pragma unroll
    for (int j = 0; j < 16; j++) {
        int c = j * 32 + lane;
        Out[row * 512 + c] = (vals[j] - mean) * rstd * g2[c] + b2[c];
    }
}

// ---------------------------------------------------------------------------
extern "C" void kernel_launch(void* const* d_in, const int* in_sizes, int n_in,
                              void* d_out, int out_size)
{
    const float* x  = (const float*)d_in[0];
    const float* wq = (const float*)d_in[1];
    const float* bq = (const float*)d_in[2];
    const float* wk = (const float*)d_in[3];
    const float* bk = (const float*)d_in[4];
    const float* wv = (const float*)d_in[5];
    const float* bv = (const float*)d_in[6];
    const float* wm = (const float*)d_in[7];
    const float* bm = (const float*)d_in[8];
    const float* g1 = (const float*)d_in[9];
    const float* b1 = (const float*)d_in[10];
    const float* g2 = (const float*)d_in[11];
    const float* b2 = (const float*)d_in[12];
    float* out = (float*)d_out;

    __half *xh, *Wqkh, *WvTh, *WmTh, *QKh, *Vth, *Wth, *Y1h;
    float *bqkp, *Wtp, *attnp, *Y1p, *mlpp;
    cudaGetSymbolAddress((void**)&xh,   g_xh);
    cudaGetSymbolAddress((void**)&Wqkh, g_Wqk_h);
    cudaGetSymbolAddress((void**)&bqkp, g_bqk);
    cudaGetSymbolAddress((void**)&WvTh, g_WvT_h);
    cudaGetSymbolAddress((void**)&WmTh, g_WmT_h);
    cudaGetSymbolAddress((void**)&QKh,  g_QK_h);
    cudaGetSymbolAddress((void**)&Vth,  g_Vt_h);
    cudaGetSymbolAddress((void**)&Wtp,  g_Wt);
    cudaGetSymbolAddress((void**)&Wth,  g_Wt_h);
    cudaGetSymbolAddress((void**)&attnp, g_attn);
    cudaGetSymbolAddress((void**)&Y1p,  g_Y1);
    cudaGetSymbolAddress((void**)&Y1h,  g_Y1_h);
    cudaGetSymbolAddress((void**)&mlpp, g_mlp);

    const int GEMM_SMEM = 98304;            // 3 x (16K A + 16K B)
    const int SC_SMEM   = 4096 + 3 * 32768; // Q + 3 key stages = 100 KB
    cudaFuncSetAttribute(hgemm_kernel, cudaFuncAttributeMaxDynamicSharedMemorySize, GEMM_SMEM);
    cudaFuncSetAttribute(scores_h_kernel, cudaFuncAttributeMaxDynamicSharedMemorySize, SC_SMEM);

    // 0) fp16 conversions (x + weights transposed/concatenated)
    prep_kernel<<<256, 256>>>(x, wq, bq, wk, bk, wv, wm);

    // 1) QK projection -> QK_h fp16   [8192 x 128]
    hgemm_kernel<<<dim3(64, 1, 1), 256, GEMM_SMEM>>>(
        xh, 512, 0, Wqkh, 512, 0, nullptr, QKh, 128, 0, 512, bqkp, nullptr);

    // 2) V transposed -> Vt_h fp16    [512 x 8192]
    hgemm_kernel<<<dim3(4, 64, 1), 256, GEMM_SMEM>>>(
        WvTh, 512, 0, xh, 512, 0, nullptr, Vth, NPOS, 0, 512, nullptr, bv);

    // 3) scores + g-fold -> Wt fp32 + Wt_h (x1/64) fp16
    scores_h_kernel<<<dim3(64, 4, 1), 256, SC_SMEM>>>(QKh, Wtp, Wth);

    // 4) attnU[z] = Wt_h[z] @ Vt_h[:, z*256:+256]^T  -> fp32 (scaled 1/64)
    hgemm_kernel<<<dim3(2, 4, 32), 256, GEMM_SMEM>>>(
        Wth, 256, 65536, Vth, NPOS, 256, attnp, nullptr, 512, 131072, 256, nullptr, nullptr);

    // 5) y1 = LN(attnU*64/Z + x) -> Y1 fp32 + Y1_h fp16
    attn_ep_kernel<<<NPOS / 8, 256>>>(Wtp, attnp, x, g1, b1, Y1p, Y1h);

    // 6) mlp = y1 @ wm + bm -> fp32
    hgemm_kernel<<<dim3(64, 4, 1), 256, GEMM_SMEM>>>(
        Y1h, 512, 0, WmTh, 512, 0, mlpp, nullptr, 512, 0, 512, bm, nullptr);

    // 7) out = LN(y1 + relu(mlp))
    mlp_ep_kernel<<<NPOS / 8, 256>>>(Y1p, mlpp, g2, b2, out);
}